// round 1
// baseline (speedup 1.0000x reference)
#include <cuda_runtime.h>
#include <cuda_bf16.h>
#include <math.h>

// ---------------------------------------------------------------------------
// TemporalMamba: B=2, L=1024, D_MODEL=1024, D_INNER=2048, D_STATE=16,
// D_CONV=4, DT_RANK=64.  All fp32.
//
// Pipeline:
//   1. xz[M,4096]   = x[M,1024] @ W_in[1024,4096]                 (SGEMM)
//   2. u[M,2048]    = silu(depthwise_conv4(xz[:, :2048]) + conv_b) (elementwise)
//   3. xdbl[M,96]   = u @ W_xproj[2048,96]                         (skinny-N GEMM)
//   4. delta[M,2048]= softplus(xdbl[:, :64] @ W_dt[64,2048] + b_dt)(SGEMM + epi)
//   5. y[M,2048]    = selective_scan(delta,u,B,C,A) + Dskip*u, * silu(z)
//   6. out[M,1024]  = y @ W_out[2048,1024]                         (SGEMM)
// ---------------------------------------------------------------------------

#define BB       2
#define LL       1024
#define DMODEL   1024
#define DINNER   2048
#define DSTATE   16
#define DCONV    4
#define DTRANK   64
#define MROWS    (BB * LL)          // 2048
#define XPROJ_N  (DTRANK + 2 * DSTATE)  // 96

// ------------------------- scratch (device globals) ------------------------
__device__ float g_xz[MROWS * 2 * DINNER];     // 32 MB  [M, 4096]
__device__ float g_u[MROWS * DINNER];          // 16 MB  [M, 2048]
__device__ float g_xdbl[MROWS * XPROJ_N];      // 0.75MB [M, 96]
__device__ float g_delta[MROWS * DINNER];      // 16 MB  [M, 2048]
__device__ float g_y[MROWS * DINNER];          // 16 MB  [M, 2048]

// ---------------------------------------------------------------------------
// Generic 128x128x8 SGEMM, row-major.  C[M,N] = A[M,K] @ B[K,N]  (+ epilogue)
// MODE 0: plain store.  MODE 1: softplus(acc + bias[col]).
// Requires M%128==0, N%128==0, K%8==0, lda%4==0, 16B-aligned base pointers.
// ---------------------------------------------------------------------------
template <int MODE>
__global__ __launch_bounds__(256)
void sgemm128(int M, int N, int K, int lda, int ldb, int ldc,
              const float* __restrict__ A, const float* __restrict__ B,
              float* __restrict__ C, const float* __restrict__ bias)
{
    const int BM = 128, BN = 128, BK = 8, TM = 8, TN = 8;
    __shared__ float As[BK][BM];
    __shared__ float Bs[BK][BN];

    const int tid = threadIdx.x;
    const int bx = blockIdx.x;   // N tile
    const int by = blockIdx.y;   // M tile

    const float* Ab = A + (size_t)by * BM * lda;
    const float* Bb = B + (size_t)bx * BN;

    const int aRow = tid >> 1;            // 0..127
    const int aCol = (tid & 1) * 4;       // 0 or 4
    const int bRow = tid >> 5;            // 0..7
    const int bCol = (tid & 31) * 4;      // 0..124

    const int tRow = (tid >> 4) * TM;     // 0..120 step 8
    const int tCol = (tid & 15) * TN;     // 0..120 step 8

    float acc[TM][TN];
#pragma unroll
    for (int i = 0; i < TM; i++)
#pragma unroll
        for (int j = 0; j < TN; j++) acc[i][j] = 0.f;

    for (int k0 = 0; k0 < K; k0 += BK) {
        float4 av = *(const float4*)(Ab + (size_t)aRow * lda + k0 + aCol);
        As[aCol + 0][aRow] = av.x;
        As[aCol + 1][aRow] = av.y;
        As[aCol + 2][aRow] = av.z;
        As[aCol + 3][aRow] = av.w;
        float4 bv = *(const float4*)(Bb + (size_t)(k0 + bRow) * ldb + bCol);
        *(float4*)&Bs[bRow][bCol] = bv;
        __syncthreads();

#pragma unroll
        for (int k = 0; k < BK; k++) {
            float4 a0 = *(const float4*)&As[k][tRow];
            float4 a1 = *(const float4*)&As[k][tRow + 4];
            float4 b0 = *(const float4*)&Bs[k][tCol];
            float4 b1 = *(const float4*)&Bs[k][tCol + 4];
            float ar[TM] = {a0.x, a0.y, a0.z, a0.w, a1.x, a1.y, a1.z, a1.w};
            float br[TN] = {b0.x, b0.y, b0.z, b0.w, b1.x, b1.y, b1.z, b1.w};
#pragma unroll
            for (int i = 0; i < TM; i++)
#pragma unroll
                for (int j = 0; j < TN; j++)
                    acc[i][j] += ar[i] * br[j];
        }
        __syncthreads();
    }

    float* Cb = C + (size_t)(by * BM) * ldc + bx * BN;
#pragma unroll
    for (int i = 0; i < TM; i++) {
        float v[TN];
#pragma unroll
        for (int j = 0; j < TN; j++) {
            float t = acc[i][j];
            if (MODE == 1) {
                t += bias[bx * BN + tCol + j];
                t = (t > 20.f) ? t : log1pf(expf(t));   // softplus
            }
            v[j] = t;
        }
        *(float4*)(Cb + (size_t)(tRow + i) * ldc + tCol)     = make_float4(v[0], v[1], v[2], v[3]);
        *(float4*)(Cb + (size_t)(tRow + i) * ldc + tCol + 4) = make_float4(v[4], v[5], v[6], v[7]);
    }
}

// ---------------------------------------------------------------------------
// Depthwise conv (width 4, left pad 3) + bias + silu.
// u[b,l,d] = silu( sum_k xz[b, l-3+k, d] * conv_w[d,k] + conv_b[d] )
// ---------------------------------------------------------------------------
__global__ __launch_bounds__(256)
void conv_silu_kernel(const float* __restrict__ xz,
                      const float* __restrict__ cw,
                      const float* __restrict__ cb,
                      float* __restrict__ u)
{
    int idx = blockIdx.x * blockDim.x + threadIdx.x;   // over B*L*DINNER = 4M
    if (idx >= MROWS * DINNER) return;
    int d   = idx & (DINNER - 1);
    int row = idx >> 11;             // b*L + l
    int l   = row & (LL - 1);

    float w0 = cw[d * 4 + 0], w1 = cw[d * 4 + 1], w2 = cw[d * 4 + 2], w3 = cw[d * 4 + 3];
    float s = cb[d];
    const float* base = xz + (size_t)row * (2 * DINNER) + d;   // row (b,l), col d
    const int stride = 2 * DINNER;
    if (l >= 3) s += base[-3 * stride] * w0;
    if (l >= 2) s += base[-2 * stride] * w1;
    if (l >= 1) s += base[-1 * stride] * w2;
    s += base[0] * w3;
    // silu
    float sg = 1.f / (1.f + expf(-s));
    u[(size_t)row * DINNER + d] = s * sg;
}

// ---------------------------------------------------------------------------
// Skinny-N GEMM: xdbl[M,96] = u[M,2048] @ W_xproj[2048,96]
// 16 rows per block, full K, 128 blocks.  Deterministic (no split-K atomics).
// ---------------------------------------------------------------------------
__global__ __launch_bounds__(256)
void gemm_xproj_kernel(const float* __restrict__ A,     // u, lda = 2048
                       const float* __restrict__ Bw,    // W_xproj [2048, 96]
                       float* __restrict__ C)           // [M, 96]
{
    const int BM = 16, BK = 32;
    __shared__ float As[BK][BM];        // transposed: As[k][row]
    __shared__ float Bs[BK][XPROJ_N];

    const int tid = threadIdx.x;
    const int rowBlock = blockIdx.x * BM;

    const int tr  = tid >> 4;           // 0..15 local row
    const int tc6 = (tid & 15) * 6;     // 0..90 col base

    float acc[6] = {0.f, 0.f, 0.f, 0.f, 0.f, 0.f};

    for (int k0 = 0; k0 < DINNER; k0 += BK) {
        // A tile: 16 rows x 32 k  (512 floats, 2 per thread)
#pragma unroll
        for (int i = tid; i < BM * BK; i += 256) {
            int r = i >> 5, c = i & 31;
            As[c][r] = A[(size_t)(rowBlock + r) * DINNER + k0 + c];
        }
        // B tile: 32 k x 96  (3072 floats, 12 per thread)
#pragma unroll
        for (int i = tid; i < BK * XPROJ_N; i += 256) {
            int r = i / XPROJ_N, c = i - r * XPROJ_N;
            Bs[r][c] = Bw[(size_t)(k0 + r) * XPROJ_N + c];
        }
        __syncthreads();
#pragma unroll
        for (int k = 0; k < BK; k++) {
            float a = As[k][tr];
#pragma unroll
            for (int j = 0; j < 6; j++)
                acc[j] += a * Bs[k][tc6 + j];
        }
        __syncthreads();
    }
#pragma unroll
    for (int j = 0; j < 6; j++)
        C[(size_t)(rowBlock + tr) * XPROJ_N + tc6 + j] = acc[j];
}

// ---------------------------------------------------------------------------
// Selective scan.  Block = 256 threads = (16 n) x (16 local d), one b per
// blockIdx.y, 16 d-channels per blockIdx.x.  B/C/delta/u/z staged in shared
// per 64-step chunk.  State h[b,d,n] lives in one register per thread.
// y[b,l,d] = (sum_n h*C + Dskip*u) * silu(z)
// ---------------------------------------------------------------------------
#define SCAN_CT 64
__global__ __launch_bounds__(256)
void scan_kernel(const float* __restrict__ delta,  // [M, 2048]
                 const float* __restrict__ u,      // [M, 2048]
                 const float* __restrict__ xz,     // [M, 4096]  (z = cols 2048+)
                 const float* __restrict__ xdbl,   // [M, 96]    (B: 64.., C: 80..)
                 const float* __restrict__ A_log,  // [2048, 16]
                 const float* __restrict__ Dskip,  // [2048]
                 float* __restrict__ y)            // [M, 2048]
{
    __shared__ float sDelta[SCAN_CT][16];
    __shared__ float sU[SCAN_CT][16];
    __shared__ float sZ[SCAN_CT][16];
    __shared__ float sB[SCAN_CT][16];
    __shared__ float sC[SCAN_CT][16];
    __shared__ float sY[SCAN_CT][16];

    const int tid = threadIdx.x;
    const int tn = tid & 15;          // state index n
    const int td = tid >> 4;          // local d
    const int dbase = blockIdx.x * 16;
    const int d = dbase + td;
    const int b = blockIdx.y;

    const float Aq  = -expf(A_log[d * DSTATE + tn]);
    const float dsk = Dskip[d];

    float h = 0.f;

    for (int t0 = 0; t0 < LL; t0 += SCAN_CT) {
        // stage tiles
#pragma unroll
        for (int i = tid; i < SCAN_CT * 16; i += 256) {
            int r = i >> 4, c = i & 15;
            int row = b * LL + t0 + r;
            sDelta[r][c] = delta[(size_t)row * DINNER + dbase + c];
            sU[r][c]     = u[(size_t)row * DINNER + dbase + c];
            sZ[r][c]     = xz[(size_t)row * (2 * DINNER) + DINNER + dbase + c];
            sB[r][c]     = xdbl[(size_t)row * XPROJ_N + DTRANK + c];
            sC[r][c]     = xdbl[(size_t)row * XPROJ_N + DTRANK + DSTATE + c];
        }
        __syncthreads();

#pragma unroll 4
        for (int tt = 0; tt < SCAN_CT; tt++) {
            float dlt = sDelta[tt][td];
            float uu  = sU[tt][td];
            float bb  = sB[tt][tn];
            float cc  = sC[tt][tn];
            float dA  = __expf(dlt * Aq);
            h = dA * h + (dlt * uu) * bb;
            float p = h * cc;
            p += __shfl_xor_sync(0xffffffffu, p, 8);
            p += __shfl_xor_sync(0xffffffffu, p, 4);
            p += __shfl_xor_sync(0xffffffffu, p, 2);
            p += __shfl_xor_sync(0xffffffffu, p, 1);
            if (tn == 0) {
                float zz = sZ[tt][td];
                float yv = p + dsk * uu;
                yv *= zz / (1.f + expf(-zz));
                sY[tt][td] = yv;
            }
        }
        __syncthreads();

#pragma unroll
        for (int i = tid; i < SCAN_CT * 16; i += 256) {
            int r = i >> 4, c = i & 15;
            int row = b * LL + t0 + r;
            y[(size_t)row * DINNER + dbase + c] = sY[r][c];
        }
        __syncthreads();
    }
}

// ---------------------------------------------------------------------------
extern "C" void kernel_launch(void* const* d_in, const int* in_sizes, int n_in,
                              void* d_out, int out_size)
{
    const float* x       = (const float*)d_in[0];  // [2,1024,1024]
    const float* W_in    = (const float*)d_in[1];  // [1024, 4096]
    const float* conv_w  = (const float*)d_in[2];  // [2048, 1, 4]
    const float* conv_b  = (const float*)d_in[3];  // [2048]
    const float* W_xproj = (const float*)d_in[4];  // [2048, 96]
    const float* W_dt    = (const float*)d_in[5];  // [64, 2048]
    const float* b_dt    = (const float*)d_in[6];  // [2048]
    const float* A_log   = (const float*)d_in[7];  // [2048, 16]
    const float* D_skip  = (const float*)d_in[8];  // [2048]
    const float* W_out   = (const float*)d_in[9];  // [2048, 1024]
    float* out = (float*)d_out;                    // [2,1024,1024]

    float* xz;    cudaGetSymbolAddress((void**)&xz,    g_xz);
    float* u;     cudaGetSymbolAddress((void**)&u,     g_u);
    float* xdbl;  cudaGetSymbolAddress((void**)&xdbl,  g_xdbl);
    float* delta; cudaGetSymbolAddress((void**)&delta, g_delta);
    float* y;     cudaGetSymbolAddress((void**)&y,     g_y);

    // 1) xz = x @ W_in                    [2048,1024]@[1024,4096]
    sgemm128<0><<<dim3(4096 / 128, MROWS / 128), 256>>>(
        MROWS, 4096, 1024, 1024, 4096, 4096, x, W_in, xz, nullptr);

    // 2) u = silu(conv(xz[:, :2048]) + conv_b)
    conv_silu_kernel<<<(MROWS * DINNER) / 256, 256>>>(xz, conv_w, conv_b, u);

    // 3) xdbl = u @ W_xproj               [2048,2048]@[2048,96]
    gemm_xproj_kernel<<<MROWS / 16, 256>>>(u, W_xproj, xdbl);

    // 4) delta = softplus(xdbl[:, :64] @ W_dt + b_dt)   [2048,64]@[64,2048]
    sgemm128<1><<<dim3(DINNER / 128, MROWS / 128), 256>>>(
        MROWS, DINNER, DTRANK, XPROJ_N, DINNER, DINNER, xdbl, W_dt, delta, b_dt);

    // 5) selective scan -> y
    scan_kernel<<<dim3(DINNER / 16, BB), 256>>>(delta, u, xz, xdbl, A_log, D_skip, y);

    // 6) out = y @ W_out                  [2048,2048]@[2048,1024]
    sgemm128<0><<<dim3(1024 / 128, MROWS / 128), 256>>>(
        MROWS, 1024, DINNER, DINNER, 1024, 1024, y, W_out, out, nullptr);
}

// round 3
// speedup vs baseline: 1.7540x; 1.7540x over previous
#include <cuda_runtime.h>
#include <cuda_bf16.h>
#include <math.h>
#include <cstdint>

// ---------------------------------------------------------------------------
// TemporalMamba: B=2, L=1024, D_MODEL=1024, D_INNER=2048, D_STATE=16,
// D_CONV=4, DT_RANK=64.
//
// NOTE: toolchain lowers PTX at compute_100 (no 'a' features) -> tcgen05 is
// unavailable. Tensor cores are reached via mma.sync.m16n8k16 (bf16x3 split).
// ---------------------------------------------------------------------------

#define BB       2
#define LL       1024
#define DMODEL   1024
#define DINNER   2048
#define DSTATE   16
#define DTRANK   64
#define MROWS    (BB * LL)                  // 2048
#define XPROJ_N  (DTRANK + 2 * DSTATE)      // 96

// ------------------------- scratch (device globals) ------------------------
__device__ float g_xz[MROWS * 2 * DINNER];      // [M, 4096]
__device__ float g_u[MROWS * DINNER];           // [M, 2048]
__device__ float g_xdbl[MROWS * XPROJ_N];       // [M, 96]
__device__ float g_delta[MROWS * DINNER];       // [M, 2048]
__device__ float g_y[MROWS * DINNER];           // [M, 2048]

// bf16 split operands
__device__ __nv_bfloat16 g_xh[MROWS * DMODEL];       // x hi      [2048,1024]
__device__ __nv_bfloat16 g_xl[MROWS * DMODEL];       // x lo
__device__ __nv_bfloat16 g_winT_h[4096 * DMODEL];    // W_in^T    [4096,1024]
__device__ __nv_bfloat16 g_winT_l[4096 * DMODEL];
__device__ __nv_bfloat16 g_yh[MROWS * DINNER];       // y hi      [2048,2048]
__device__ __nv_bfloat16 g_yl[MROWS * DINNER];
__device__ __nv_bfloat16 g_woutT_h[DMODEL * DINNER]; // W_out^T   [1024,2048]
__device__ __nv_bfloat16 g_woutT_l[DMODEL * DINNER];

// ---------------------------------------------------------------------------
// mma.sync / ldmatrix / cp.async helpers (all valid at compute_100)
// ---------------------------------------------------------------------------
__device__ __forceinline__ uint32_t smem_u32(const void* p) {
    uint32_t a;
    asm("{ .reg .u64 t; cvta.to.shared.u64 t, %1; cvt.u32.u64 %0, t; }" : "=r"(a) : "l"(p));
    return a;
}
__device__ __forceinline__ void cpa16(uint32_t s, const void* g) {
    asm volatile("cp.async.cg.shared.global [%0], [%1], 16;" :: "r"(s), "l"(g));
}
__device__ __forceinline__ void ldsm4(uint32_t& r0, uint32_t& r1, uint32_t& r2, uint32_t& r3,
                                      uint32_t addr) {
    asm volatile("ldmatrix.sync.aligned.m8n8.x4.shared.b16 {%0,%1,%2,%3}, [%4];"
                 : "=r"(r0), "=r"(r1), "=r"(r2), "=r"(r3) : "r"(addr));
}
__device__ __forceinline__ void mma16816(float& c0, float& c1, float& c2, float& c3,
                                         uint32_t a0, uint32_t a1, uint32_t a2, uint32_t a3,
                                         uint32_t b0, uint32_t b1) {
    asm volatile(
        "mma.sync.aligned.m16n8k16.row.col.f32.bf16.bf16.f32 "
        "{%0,%1,%2,%3}, {%4,%5,%6,%7}, {%8,%9}, {%0,%1,%2,%3};"
        : "+f"(c0), "+f"(c1), "+f"(c2), "+f"(c3)
        : "r"(a0), "r"(a1), "r"(a2), "r"(a3), "r"(b0), "r"(b1));
}

// ---------------------------------------------------------------------------
// bf16x3 split tensor-core GEMM:  C[M,N] = (Ah+Al)[M,K] @ (Bh+Bl)^T
//   A row-major [M][K], B as Bt[N][K] (K-major) -> both plain ldmatrix.x4.
//   CTA: 256 thr = 8 warps (2 M x 4 N), tile 128x128, BK=64, cp.async
//   double buffer.  Split terms: AhBh + AhBl + AlBh, fp32 accumulate.
// ---------------------------------------------------------------------------
#define SSTR     72                                  // smem row stride (bf16)
#define TILE_B   (128 * SSTR * 2)                    // 18432 B per tile
#define STAGE_B  (4 * TILE_B)                        // Ah, Al, Bh, Bl
#define GM_SMEM  (2 * STAGE_B)                       // 147456 B

__device__ __forceinline__ void load_stage_tile(
    const __nv_bfloat16* __restrict__ G, int rowBase, int k0, int K,
    uint32_t sdst, int tid)
{
#pragma unroll
    for (int i = 0; i < 4; i++) {
        int idx = tid + i * 256;            // 0..1023
        int r = idx >> 3;                   // row 0..127
        int q = idx & 7;                    // 16B chunk in row
        const void* g = G + (size_t)(rowBase + r) * K + k0 + q * 8;
        cpa16(sdst + (uint32_t)(r * SSTR + q * 8) * 2, g);
    }
}

__global__ __launch_bounds__(256, 1)
void gemm_mma(const __nv_bfloat16* __restrict__ Ah, const __nv_bfloat16* __restrict__ Al,
              const __nv_bfloat16* __restrict__ Bh, const __nv_bfloat16* __restrict__ Bl,
              float* __restrict__ C, int K, int ldc)
{
    extern __shared__ __align__(16) char dsm[];
    const uint32_t sbase = smem_u32(dsm);

    const int tid  = threadIdx.x;
    const int wid  = tid >> 5;
    const int lane = tid & 31;
    const int wm   = wid >> 2;              // 0..1
    const int wn   = wid & 3;               // 0..3
    const int bx   = blockIdx.x, by = blockIdx.y;

    // ldmatrix lane addressing
    const int aRow  = lane & 15;
    const int aCsel = (lane >> 4) * 8;
    const int bRow  = (lane & 7) + ((lane >> 4) << 3);
    const int bCsel = ((lane >> 3) & 1) * 8;

    float acc[4][4][4];
#pragma unroll
    for (int i = 0; i < 4; i++)
#pragma unroll
        for (int j = 0; j < 4; j++)
#pragma unroll
            for (int v = 0; v < 4; v++) acc[i][j][v] = 0.f;

    const int NC = K >> 6;

    // prologue: stage 0 loads chunk 0
    load_stage_tile(Ah, by * 128, 0, K, sbase + 0 * TILE_B, tid);
    load_stage_tile(Al, by * 128, 0, K, sbase + 1 * TILE_B, tid);
    load_stage_tile(Bh, bx * 128, 0, K, sbase + 2 * TILE_B, tid);
    load_stage_tile(Bl, bx * 128, 0, K, sbase + 3 * TILE_B, tid);
    asm volatile("cp.async.commit_group;");

    for (int c = 0; c < NC; c++) {
        if (c + 1 < NC) {
            const uint32_t sd = sbase + ((c + 1) & 1) * STAGE_B;
            const int k0 = (c + 1) << 6;
            load_stage_tile(Ah, by * 128, k0, K, sd + 0 * TILE_B, tid);
            load_stage_tile(Al, by * 128, k0, K, sd + 1 * TILE_B, tid);
            load_stage_tile(Bh, bx * 128, k0, K, sd + 2 * TILE_B, tid);
            load_stage_tile(Bl, bx * 128, k0, K, sd + 3 * TILE_B, tid);
            asm volatile("cp.async.commit_group;");
            asm volatile("cp.async.wait_group 1;");
        } else {
            asm volatile("cp.async.wait_group 0;");
        }
        __syncthreads();

        const uint32_t st = sbase + (c & 1) * STAGE_B;
        // per-warp smem base addrs (element offsets; *2 for bytes)
        const uint32_t sAh = st + 0 * TILE_B;
        const uint32_t sAl = st + 1 * TILE_B;
        const uint32_t sBh = st + 2 * TILE_B;
        const uint32_t sBl = st + 3 * TILE_B;

#pragma unroll
        for (int kk = 0; kk < 64; kk += 16) {
            uint32_t ah[4][4], al[4][4], bh[2][4], bl[2][4];
#pragma unroll
            for (int i = 0; i < 4; i++) {
                uint32_t off = (uint32_t)((wm * 64 + i * 16 + aRow) * SSTR + kk + aCsel) * 2;
                ldsm4(ah[i][0], ah[i][1], ah[i][2], ah[i][3], sAh + off);
            }
#pragma unroll
            for (int j2 = 0; j2 < 2; j2++) {
                uint32_t off = (uint32_t)((wn * 32 + j2 * 16 + bRow) * SSTR + kk + bCsel) * 2;
                ldsm4(bh[j2][0], bh[j2][1], bh[j2][2], bh[j2][3], sBh + off);
            }
            // hh
#pragma unroll
            for (int i = 0; i < 4; i++)
#pragma unroll
                for (int j = 0; j < 4; j++) {
                    const uint32_t* b = bh[j >> 1] + (j & 1) * 2;
                    mma16816(acc[i][j][0], acc[i][j][1], acc[i][j][2], acc[i][j][3],
                             ah[i][0], ah[i][1], ah[i][2], ah[i][3], b[0], b[1]);
                }
            // hl
#pragma unroll
            for (int j2 = 0; j2 < 2; j2++) {
                uint32_t off = (uint32_t)((wn * 32 + j2 * 16 + bRow) * SSTR + kk + bCsel) * 2;
                ldsm4(bl[j2][0], bl[j2][1], bl[j2][2], bl[j2][3], sBl + off);
            }
#pragma unroll
            for (int i = 0; i < 4; i++)
#pragma unroll
                for (int j = 0; j < 4; j++) {
                    const uint32_t* b = bl[j >> 1] + (j & 1) * 2;
                    mma16816(acc[i][j][0], acc[i][j][1], acc[i][j][2], acc[i][j][3],
                             ah[i][0], ah[i][1], ah[i][2], ah[i][3], b[0], b[1]);
                }
            // lh
#pragma unroll
            for (int i = 0; i < 4; i++) {
                uint32_t off = (uint32_t)((wm * 64 + i * 16 + aRow) * SSTR + kk + aCsel) * 2;
                ldsm4(al[i][0], al[i][1], al[i][2], al[i][3], sAl + off);
            }
#pragma unroll
            for (int i = 0; i < 4; i++)
#pragma unroll
                for (int j = 0; j < 4; j++) {
                    const uint32_t* b = bh[j >> 1] + (j & 1) * 2;
                    mma16816(acc[i][j][0], acc[i][j][1], acc[i][j][2], acc[i][j][3],
                             al[i][0], al[i][1], al[i][2], al[i][3], b[0], b[1]);
                }
        }
        __syncthreads();
    }

    // epilogue: direct fp32 stores (float2 pairs)
    const int mBase = by * 128 + wm * 64;
    const int nBase = bx * 128 + wn * 32;
    const int r0 = lane >> 2;
    const int c0 = (lane & 3) * 2;
#pragma unroll
    for (int i = 0; i < 4; i++) {
#pragma unroll
        for (int j = 0; j < 4; j++) {
            float* p0 = C + (size_t)(mBase + i * 16 + r0) * ldc + nBase + j * 8 + c0;
            *(float2*)p0                    = make_float2(acc[i][j][0], acc[i][j][1]);
            *(float2*)(p0 + (size_t)8 * ldc) = make_float2(acc[i][j][2], acc[i][j][3]);
        }
    }
}

// ---------------------------------------------------------------------------
// fp32 -> bf16 hi/lo split (row-major)
// ---------------------------------------------------------------------------
__global__ __launch_bounds__(256)
void split_fp32_bf16(const float* __restrict__ in, __nv_bfloat16* __restrict__ hi,
                     __nv_bfloat16* __restrict__ lo, int n)
{
    int i = blockIdx.x * 256 + threadIdx.x;
    if (i >= n) return;
    float a = in[i];
    __nv_bfloat16 h = __float2bfloat16(a);
    hi[i] = h;
    lo[i] = __float2bfloat16(a - __bfloat162float(h));
}

// transpose + split:  in[K][N] fp32  ->  hiT/loT [N][K] bf16
__global__ __launch_bounds__(256)
void tsplit_fp32_bf16(const float* __restrict__ in,
                      __nv_bfloat16* __restrict__ hiT, __nv_bfloat16* __restrict__ loT,
                      int K, int N)
{
    __shared__ float t[32][33];
    int tx = threadIdx.x & 31;
    int ty = threadIdx.x >> 5;
    int n0 = blockIdx.x * 32;
    int k0 = blockIdx.y * 32;
#pragma unroll
    for (int j = 0; j < 4; j++) {
        int kk = ty + j * 8;
        t[kk][tx] = in[(size_t)(k0 + kk) * N + n0 + tx];
    }
    __syncthreads();
#pragma unroll
    for (int j = 0; j < 4; j++) {
        int a = ty + j * 8;
        float v = t[tx][a];
        __nv_bfloat16 h = __float2bfloat16(v);
        hiT[(size_t)(n0 + a) * K + k0 + tx] = h;
        loT[(size_t)(n0 + a) * K + k0 + tx] = __float2bfloat16(v - __bfloat162float(h));
    }
}

// ---------------------------------------------------------------------------
// fp32 SGEMM (delta GEMM only).  MODE 1: softplus(acc+bias).
// ---------------------------------------------------------------------------
template <int MODE>
__global__ __launch_bounds__(256)
void sgemm128(int M, int N, int K, int lda, int ldb, int ldc,
              const float* __restrict__ A, const float* __restrict__ B,
              float* __restrict__ C, const float* __restrict__ bias)
{
    const int BM = 128, BN = 128, BK = 8, TM = 8, TN = 8;
    __shared__ float As[BK][BM];
    __shared__ float Bs[BK][BN];

    const int tid = threadIdx.x;
    const int bx = blockIdx.x, by = blockIdx.y;

    const float* Ab = A + (size_t)by * BM * lda;
    const float* Bb = B + (size_t)bx * BN;

    const int aRow = tid >> 1;
    const int aCol = (tid & 1) * 4;
    const int bRow = tid >> 5;
    const int bCol = (tid & 31) * 4;
    const int tRow = (tid >> 4) * TM;
    const int tCol = (tid & 15) * TN;

    float acc[TM][TN];
#pragma unroll
    for (int i = 0; i < TM; i++)
#pragma unroll
        for (int j = 0; j < TN; j++) acc[i][j] = 0.f;

    for (int k0 = 0; k0 < K; k0 += BK) {
        float4 av = *(const float4*)(Ab + (size_t)aRow * lda + k0 + aCol);
        As[aCol + 0][aRow] = av.x;
        As[aCol + 1][aRow] = av.y;
        As[aCol + 2][aRow] = av.z;
        As[aCol + 3][aRow] = av.w;
        float4 bv = *(const float4*)(Bb + (size_t)(k0 + bRow) * ldb + bCol);
        *(float4*)&Bs[bRow][bCol] = bv;
        __syncthreads();

#pragma unroll
        for (int k = 0; k < BK; k++) {
            float4 a0 = *(const float4*)&As[k][tRow];
            float4 a1 = *(const float4*)&As[k][tRow + 4];
            float4 b0 = *(const float4*)&Bs[k][tCol];
            float4 b1 = *(const float4*)&Bs[k][tCol + 4];
            float ar[TM] = {a0.x, a0.y, a0.z, a0.w, a1.x, a1.y, a1.z, a1.w};
            float br[TN] = {b0.x, b0.y, b0.z, b0.w, b1.x, b1.y, b1.z, b1.w};
#pragma unroll
            for (int i = 0; i < TM; i++)
#pragma unroll
                for (int j = 0; j < TN; j++)
                    acc[i][j] += ar[i] * br[j];
        }
        __syncthreads();
    }

    float* Cb = C + (size_t)(by * BM) * ldc + bx * BN;
#pragma unroll
    for (int i = 0; i < TM; i++) {
        float v[TN];
#pragma unroll
        for (int j = 0; j < TN; j++) {
            float t = acc[i][j];
            if (MODE == 1) {
                t += bias[bx * BN + tCol + j];
                t = (t > 20.f) ? t : log1pf(expf(t));
            }
            v[j] = t;
        }
        *(float4*)(Cb + (size_t)(tRow + i) * ldc + tCol)     = make_float4(v[0], v[1], v[2], v[3]);
        *(float4*)(Cb + (size_t)(tRow + i) * ldc + tCol + 4) = make_float4(v[4], v[5], v[6], v[7]);
    }
}

// ---------------------------------------------------------------------------
// depthwise conv(4) + bias + silu
// ---------------------------------------------------------------------------
__global__ __launch_bounds__(256)
void conv_silu_kernel(const float* __restrict__ xz,
                      const float* __restrict__ cw,
                      const float* __restrict__ cb,
                      float* __restrict__ u)
{
    int idx = blockIdx.x * blockDim.x + threadIdx.x;
    if (idx >= MROWS * DINNER) return;
    int d   = idx & (DINNER - 1);
    int row = idx >> 11;
    int l   = row & (LL - 1);

    float w0 = cw[d * 4 + 0], w1 = cw[d * 4 + 1], w2 = cw[d * 4 + 2], w3 = cw[d * 4 + 3];
    float s = cb[d];
    const float* base = xz + (size_t)row * (2 * DINNER) + d;
    const int stride = 2 * DINNER;
    if (l >= 3) s += base[-3 * stride] * w0;
    if (l >= 2) s += base[-2 * stride] * w1;
    if (l >= 1) s += base[-1 * stride] * w2;
    s += base[0] * w3;
    float sg = 1.f / (1.f + expf(-s));
    u[(size_t)row * DINNER + d] = s * sg;
}

// ---------------------------------------------------------------------------
// skinny-N GEMM: xdbl[M,96] = u[M,2048] @ W_xproj[2048,96]
// ---------------------------------------------------------------------------
__global__ __launch_bounds__(256)
void gemm_xproj_kernel(const float* __restrict__ A,
                       const float* __restrict__ Bw,
                       float* __restrict__ C)
{
    const int BM = 16, BK = 32;
    __shared__ float As[BK][BM];
    __shared__ float Bs[BK][XPROJ_N];

    const int tid = threadIdx.x;
    const int rowBlock = blockIdx.x * BM;
    const int tr  = tid >> 4;
    const int tc6 = (tid & 15) * 6;

    float acc[6] = {0.f, 0.f, 0.f, 0.f, 0.f, 0.f};

    for (int k0 = 0; k0 < DINNER; k0 += BK) {
#pragma unroll
        for (int i = tid; i < BM * BK; i += 256) {
            int r = i >> 5, c = i & 31;
            As[c][r] = A[(size_t)(rowBlock + r) * DINNER + k0 + c];
        }
#pragma unroll
        for (int i = tid; i < BK * XPROJ_N; i += 256) {
            int r = i / XPROJ_N, c = i - r * XPROJ_N;
            Bs[r][c] = Bw[(size_t)(k0 + r) * XPROJ_N + c];
        }
        __syncthreads();
#pragma unroll
        for (int k = 0; k < BK; k++) {
            float a = As[k][tr];
#pragma unroll
            for (int j = 0; j < 6; j++)
                acc[j] += a * Bs[k][tc6 + j];
        }
        __syncthreads();
    }
#pragma unroll
    for (int j = 0; j < 6; j++)
        C[(size_t)(rowBlock + tr) * XPROJ_N + tc6 + j] = acc[j];
}

// ---------------------------------------------------------------------------
// selective scan
// ---------------------------------------------------------------------------
#define SCAN_CT 64
__global__ __launch_bounds__(256)
void scan_kernel(const float* __restrict__ delta,
                 const float* __restrict__ u,
                 const float* __restrict__ xz,
                 const float* __restrict__ xdbl,
                 const float* __restrict__ A_log,
                 const float* __restrict__ Dskip,
                 float* __restrict__ y)
{
    __shared__ float sDelta[SCAN_CT][16];
    __shared__ float sU[SCAN_CT][16];
    __shared__ float sZ[SCAN_CT][16];
    __shared__ float sB[SCAN_CT][16];
    __shared__ float sC[SCAN_CT][16];
    __shared__ float sY[SCAN_CT][16];

    const int tid = threadIdx.x;
    const int tn = tid & 15;
    const int td = tid >> 4;
    const int dbase = blockIdx.x * 16;
    const int d = dbase + td;
    const int b = blockIdx.y;

    const float Aq  = -expf(A_log[d * DSTATE + tn]);
    const float dsk = Dskip[d];

    float h = 0.f;

    for (int t0 = 0; t0 < LL; t0 += SCAN_CT) {
#pragma unroll
        for (int i = tid; i < SCAN_CT * 16; i += 256) {
            int r = i >> 4, c = i & 15;
            int row = b * LL + t0 + r;
            sDelta[r][c] = delta[(size_t)row * DINNER + dbase + c];
            sU[r][c]     = u[(size_t)row * DINNER + dbase + c];
            sZ[r][c]     = xz[(size_t)row * (2 * DINNER) + DINNER + dbase + c];
            sB[r][c]     = xdbl[(size_t)row * XPROJ_N + DTRANK + c];
            sC[r][c]     = xdbl[(size_t)row * XPROJ_N + DTRANK + DSTATE + c];
        }
        __syncthreads();

#pragma unroll 4
        for (int tt = 0; tt < SCAN_CT; tt++) {
            float dlt = sDelta[tt][td];
            float uu  = sU[tt][td];
            float bb  = sB[tt][tn];
            float cc  = sC[tt][tn];
            float dA  = __expf(dlt * Aq);
            h = dA * h + (dlt * uu) * bb;
            float p = h * cc;
            p += __shfl_xor_sync(0xffffffffu, p, 8);
            p += __shfl_xor_sync(0xffffffffu, p, 4);
            p += __shfl_xor_sync(0xffffffffu, p, 2);
            p += __shfl_xor_sync(0xffffffffu, p, 1);
            if (tn == 0) {
                float zz = sZ[tt][td];
                float yv = p + dsk * uu;
                yv *= zz / (1.f + expf(-zz));
                sY[tt][td] = yv;
            }
        }
        __syncthreads();

#pragma unroll
        for (int i = tid; i < SCAN_CT * 16; i += 256) {
            int r = i >> 4, c = i & 15;
            int row = b * LL + t0 + r;
            y[(size_t)row * DINNER + dbase + c] = sY[r][c];
        }
        __syncthreads();
    }
}

// ---------------------------------------------------------------------------
extern "C" void kernel_launch(void* const* d_in, const int* in_sizes, int n_in,
                              void* d_out, int out_size)
{
    const float* x       = (const float*)d_in[0];  // [2,1024,1024]
    const float* W_in    = (const float*)d_in[1];  // [1024, 4096]
    const float* conv_w  = (const float*)d_in[2];  // [2048, 1, 4]
    const float* conv_b  = (const float*)d_in[3];  // [2048]
    const float* W_xproj = (const float*)d_in[4];  // [2048, 96]
    const float* W_dt    = (const float*)d_in[5];  // [64, 2048]
    const float* b_dt    = (const float*)d_in[6];  // [2048]
    const float* A_log   = (const float*)d_in[7];  // [2048, 16]
    const float* D_skip  = (const float*)d_in[8];  // [2048]
    const float* W_out   = (const float*)d_in[9];  // [2048, 1024]
    float* out = (float*)d_out;                    // [2,1024,1024]

    float* xz;    cudaGetSymbolAddress((void**)&xz,    g_xz);
    float* u;     cudaGetSymbolAddress((void**)&u,     g_u);
    float* xdbl;  cudaGetSymbolAddress((void**)&xdbl,  g_xdbl);
    float* delta; cudaGetSymbolAddress((void**)&delta, g_delta);
    float* y;     cudaGetSymbolAddress((void**)&y,     g_y);

    __nv_bfloat16 *xh, *xl, *winTh, *winTl, *yh, *yl, *woutTh, *woutTl;
    cudaGetSymbolAddress((void**)&xh,     g_xh);
    cudaGetSymbolAddress((void**)&xl,     g_xl);
    cudaGetSymbolAddress((void**)&winTh,  g_winT_h);
    cudaGetSymbolAddress((void**)&winTl,  g_winT_l);
    cudaGetSymbolAddress((void**)&yh,     g_yh);
    cudaGetSymbolAddress((void**)&yl,     g_yl);
    cudaGetSymbolAddress((void**)&woutTh, g_woutT_h);
    cudaGetSymbolAddress((void**)&woutTl, g_woutT_l);

    cudaFuncSetAttribute(gemm_mma, cudaFuncAttributeMaxDynamicSharedMemorySize, GM_SMEM);

    // operand conversions
    split_fp32_bf16<<<(MROWS * DMODEL) / 256, 256>>>(x, xh, xl, MROWS * DMODEL);
    tsplit_fp32_bf16<<<dim3(4096 / 32, DMODEL / 32), 256>>>(W_in, winTh, winTl, DMODEL, 4096);
    tsplit_fp32_bf16<<<dim3(DMODEL / 32, DINNER / 32), 256>>>(W_out, woutTh, woutTl, DINNER, DMODEL);

    // 1) xz = x @ W_in        [2048,1024] @ [1024,4096]   (tensor cores)
    gemm_mma<<<dim3(4096 / 128, MROWS / 128), 256, GM_SMEM>>>(
        xh, xl, winTh, winTl, xz, DMODEL, 4096);

    // 2) u = silu(conv(xz[:, :2048]) + conv_b)
    conv_silu_kernel<<<(MROWS * DINNER) / 256, 256>>>(xz, conv_w, conv_b, u);

    // 3) xdbl = u @ W_xproj
    gemm_xproj_kernel<<<MROWS / 16, 256>>>(u, W_xproj, xdbl);

    // 4) delta = softplus(xdbl[:, :64] @ W_dt + b_dt)
    sgemm128<1><<<dim3(DINNER / 128, MROWS / 128), 256>>>(
        MROWS, DINNER, DTRANK, XPROJ_N, DINNER, DINNER, xdbl, W_dt, delta, b_dt);

    // 5) selective scan -> y
    scan_kernel<<<dim3(DINNER / 16, BB), 256>>>(delta, u, xz, xdbl, A_log, D_skip, y);

    // 6) out = y @ W_out      [2048,2048] @ [2048,1024]   (tensor cores)
    split_fp32_bf16<<<(MROWS * DINNER) / 256, 256>>>(y, yh, yl, MROWS * DINNER);
    gemm_mma<<<dim3(1024 / 128, MROWS / 128), 256, GM_SMEM>>>(
        yh, yl, woutTh, woutTl, out, DINNER, 1024);
}

// round 5
// speedup vs baseline: 1.9212x; 1.0953x over previous
#include <cuda_runtime.h>
#include <cuda_bf16.h>
#include <math.h>
#include <cstdint>

// ---------------------------------------------------------------------------
// TemporalMamba: B=2, L=1024, D_MODEL=1024, D_INNER=2048, D_STATE=16,
// D_CONV=4, DT_RANK=64.
// Tensor cores via mma.sync.m16n8k16 bf16x3 split (toolchain is compute_100
// base: tcgen05 unavailable).
// ---------------------------------------------------------------------------

#define BB       2
#define LL       1024
#define DMODEL   1024
#define DINNER   2048
#define DSTATE   16
#define DTRANK   64
#define MROWS    (BB * LL)                  // 2048
#define XPROJ_N  (DTRANK + 2 * DSTATE)      // 96
#define KSPLITS  8

// ------------------------- scratch (device globals) ------------------------
__device__ float g_xz[MROWS * 2 * DINNER];      // [M, 4096]
__device__ float g_u[MROWS * DINNER];           // [M, 2048]
__device__ float g_xdbl[MROWS * XPROJ_N];       // [M, 96]
__device__ float g_delta[MROWS * DINNER];       // [M, 2048]
__device__ float g_xpart[KSPLITS * MROWS * XPROJ_N];  // split-K partials

// bf16 split operands
__device__ __nv_bfloat16 g_xh[MROWS * DMODEL];
__device__ __nv_bfloat16 g_xl[MROWS * DMODEL];
__device__ __nv_bfloat16 g_winT_h[4096 * DMODEL];
__device__ __nv_bfloat16 g_winT_l[4096 * DMODEL];
__device__ __nv_bfloat16 g_yh[MROWS * DINNER];
__device__ __nv_bfloat16 g_yl[MROWS * DINNER];
__device__ __nv_bfloat16 g_woutT_h[DMODEL * DINNER];
__device__ __nv_bfloat16 g_woutT_l[DMODEL * DINNER];

// ---------------------------------------------------------------------------
// mma.sync / ldmatrix / cp.async helpers
// ---------------------------------------------------------------------------
__device__ __forceinline__ uint32_t smem_u32(const void* p) {
    uint32_t a;
    asm("{ .reg .u64 t; cvta.to.shared.u64 t, %1; cvt.u32.u64 %0, t; }" : "=r"(a) : "l"(p));
    return a;
}
__device__ __forceinline__ void cpa16(uint32_t s, const void* g) {
    asm volatile("cp.async.cg.shared.global [%0], [%1], 16;" :: "r"(s), "l"(g));
}
__device__ __forceinline__ void ldsm4(uint32_t& r0, uint32_t& r1, uint32_t& r2, uint32_t& r3,
                                      uint32_t addr) {
    asm volatile("ldmatrix.sync.aligned.m8n8.x4.shared.b16 {%0,%1,%2,%3}, [%4];"
                 : "=r"(r0), "=r"(r1), "=r"(r2), "=r"(r3) : "r"(addr));
}
__device__ __forceinline__ void mma16816(float& c0, float& c1, float& c2, float& c3,
                                         uint32_t a0, uint32_t a1, uint32_t a2, uint32_t a3,
                                         uint32_t b0, uint32_t b1) {
    asm volatile(
        "mma.sync.aligned.m16n8k16.row.col.f32.bf16.bf16.f32 "
        "{%0,%1,%2,%3}, {%4,%5,%6,%7}, {%8,%9}, {%0,%1,%2,%3};"
        : "+f"(c0), "+f"(c1), "+f"(c2), "+f"(c3)
        : "r"(a0), "r"(a1), "r"(a2), "r"(a3), "r"(b0), "r"(b1));
}

// ---------------------------------------------------------------------------
// bf16x3 split tensor-core GEMM:  C[M,N] = (Ah+Al)[M,K] @ (Bh+Bl)^T
//   A row-major [M][K], B as Bt[N][K] (K-major).  CTA: 512 thr = 16 warps
//   (4 M x 4 N), tile 128x128, warp tile 32x32, BK=64, cp.async double
//   buffer.  Terms: AhBh + AhBl + AlBh, fp32 accumulate.
// ---------------------------------------------------------------------------
#define SSTR     72                                  // smem row stride (bf16)
#define TILE_B   (128 * SSTR * 2)                    // 18432 B per tile
#define STAGE_B  (4 * TILE_B)                        // Ah, Al, Bh, Bl
#define GM_SMEM  (2 * STAGE_B)                       // 147456 B

__device__ __forceinline__ void load_stage_tile(
    const __nv_bfloat16* __restrict__ G, int rowBase, int k0, int K,
    uint32_t sdst, int tid)
{
#pragma unroll
    for (int i = 0; i < 2; i++) {
        int idx = tid + i * 512;            // 0..1023
        int r = idx >> 3;                   // row 0..127
        int q = idx & 7;                    // 16B chunk in row
        const void* g = G + (size_t)(rowBase + r) * K + k0 + q * 8;
        cpa16(sdst + (uint32_t)(r * SSTR + q * 8) * 2, g);
    }
}

__global__ __launch_bounds__(512, 1)
void gemm_mma(const __nv_bfloat16* __restrict__ Ah, const __nv_bfloat16* __restrict__ Al,
              const __nv_bfloat16* __restrict__ Bh, const __nv_bfloat16* __restrict__ Bl,
              float* __restrict__ C, int K, int ldc)
{
    extern __shared__ __align__(16) char dsm[];
    const uint32_t sbase = smem_u32(dsm);

    const int tid  = threadIdx.x;
    const int wid  = tid >> 5;              // 0..15
    const int lane = tid & 31;
    const int wm   = wid >> 2;              // 0..3  (M)
    const int wn   = wid & 3;               // 0..3  (N)
    const int bx   = blockIdx.x, by = blockIdx.y;

    const int aRow  = lane & 15;
    const int aCsel = (lane >> 4) * 8;
    const int bRow  = (lane & 7) + ((lane >> 4) << 3);
    const int bCsel = ((lane >> 3) & 1) * 8;

    float acc[2][4][4];
#pragma unroll
    for (int i = 0; i < 2; i++)
#pragma unroll
        for (int j = 0; j < 4; j++)
#pragma unroll
            for (int v = 0; v < 4; v++) acc[i][j][v] = 0.f;

    const int NC = K >> 6;

    load_stage_tile(Ah, by * 128, 0, K, sbase + 0 * TILE_B, tid);
    load_stage_tile(Al, by * 128, 0, K, sbase + 1 * TILE_B, tid);
    load_stage_tile(Bh, bx * 128, 0, K, sbase + 2 * TILE_B, tid);
    load_stage_tile(Bl, bx * 128, 0, K, sbase + 3 * TILE_B, tid);
    asm volatile("cp.async.commit_group;");

    for (int c = 0; c < NC; c++) {
        if (c + 1 < NC) {
            const uint32_t sd = sbase + ((c + 1) & 1) * STAGE_B;
            const int k0 = (c + 1) << 6;
            load_stage_tile(Ah, by * 128, k0, K, sd + 0 * TILE_B, tid);
            load_stage_tile(Al, by * 128, k0, K, sd + 1 * TILE_B, tid);
            load_stage_tile(Bh, bx * 128, k0, K, sd + 2 * TILE_B, tid);
            load_stage_tile(Bl, bx * 128, k0, K, sd + 3 * TILE_B, tid);
            asm volatile("cp.async.commit_group;");
            asm volatile("cp.async.wait_group 1;");
        } else {
            asm volatile("cp.async.wait_group 0;");
        }
        __syncthreads();

        const uint32_t st = sbase + (c & 1) * STAGE_B;
        const uint32_t sAh = st + 0 * TILE_B;
        const uint32_t sAl = st + 1 * TILE_B;
        const uint32_t sBh = st + 2 * TILE_B;
        const uint32_t sBl = st + 3 * TILE_B;

#pragma unroll
        for (int kk = 0; kk < 64; kk += 16) {
            uint32_t ah[2][4], al[2][4], bh[2][4], bl[2][4];
#pragma unroll
            for (int i = 0; i < 2; i++) {
                uint32_t off = (uint32_t)((wm * 32 + i * 16 + aRow) * SSTR + kk + aCsel) * 2;
                ldsm4(ah[i][0], ah[i][1], ah[i][2], ah[i][3], sAh + off);
            }
#pragma unroll
            for (int j2 = 0; j2 < 2; j2++) {
                uint32_t off = (uint32_t)((wn * 32 + j2 * 16 + bRow) * SSTR + kk + bCsel) * 2;
                ldsm4(bh[j2][0], bh[j2][1], bh[j2][2], bh[j2][3], sBh + off);
            }
            // hh
#pragma unroll
            for (int i = 0; i < 2; i++)
#pragma unroll
                for (int j = 0; j < 4; j++) {
                    const uint32_t* b = bh[j >> 1] + (j & 1) * 2;
                    mma16816(acc[i][j][0], acc[i][j][1], acc[i][j][2], acc[i][j][3],
                             ah[i][0], ah[i][1], ah[i][2], ah[i][3], b[0], b[1]);
                }
            // hl
#pragma unroll
            for (int j2 = 0; j2 < 2; j2++) {
                uint32_t off = (uint32_t)((wn * 32 + j2 * 16 + bRow) * SSTR + kk + bCsel) * 2;
                ldsm4(bl[j2][0], bl[j2][1], bl[j2][2], bl[j2][3], sBl + off);
            }
#pragma unroll
            for (int i = 0; i < 2; i++)
#pragma unroll
                for (int j = 0; j < 4; j++) {
                    const uint32_t* b = bl[j >> 1] + (j & 1) * 2;
                    mma16816(acc[i][j][0], acc[i][j][1], acc[i][j][2], acc[i][j][3],
                             ah[i][0], ah[i][1], ah[i][2], ah[i][3], b[0], b[1]);
                }
            // lh
#pragma unroll
            for (int i = 0; i < 2; i++) {
                uint32_t off = (uint32_t)((wm * 32 + i * 16 + aRow) * SSTR + kk + aCsel) * 2;
                ldsm4(al[i][0], al[i][1], al[i][2], al[i][3], sAl + off);
            }
#pragma unroll
            for (int i = 0; i < 2; i++)
#pragma unroll
                for (int j = 0; j < 4; j++) {
                    const uint32_t* b = bh[j >> 1] + (j & 1) * 2;
                    mma16816(acc[i][j][0], acc[i][j][1], acc[i][j][2], acc[i][j][3],
                             al[i][0], al[i][1], al[i][2], al[i][3], b[0], b[1]);
                }
        }
        __syncthreads();
    }

    const int mBase = by * 128 + wm * 32;
    const int nBase = bx * 128 + wn * 32;
    const int r0 = lane >> 2;
    const int c0 = (lane & 3) * 2;
#pragma unroll
    for (int i = 0; i < 2; i++) {
#pragma unroll
        for (int j = 0; j < 4; j++) {
            float* p0 = C + (size_t)(mBase + i * 16 + r0) * ldc + nBase + j * 8 + c0;
            *(float2*)p0                     = make_float2(acc[i][j][0], acc[i][j][1]);
            *(float2*)(p0 + (size_t)8 * ldc) = make_float2(acc[i][j][2], acc[i][j][3]);
        }
    }
}

// ---------------------------------------------------------------------------
// fp32 -> bf16 hi/lo split (row-major)
// ---------------------------------------------------------------------------
__global__ __launch_bounds__(256)
void split_fp32_bf16(const float* __restrict__ in, __nv_bfloat16* __restrict__ hi,
                     __nv_bfloat16* __restrict__ lo, int n)
{
    int i = blockIdx.x * 256 + threadIdx.x;
    if (i >= n) return;
    float a = in[i];
    __nv_bfloat16 h = __float2bfloat16(a);
    hi[i] = h;
    lo[i] = __float2bfloat16(a - __bfloat162float(h));
}

// transpose + split:  in[K][N] fp32  ->  hiT/loT [N][K] bf16
__global__ __launch_bounds__(256)
void tsplit_fp32_bf16(const float* __restrict__ in,
                      __nv_bfloat16* __restrict__ hiT, __nv_bfloat16* __restrict__ loT,
                      int K, int N)
{
    __shared__ float t[32][33];
    int tx = threadIdx.x & 31;
    int ty = threadIdx.x >> 5;
    int n0 = blockIdx.x * 32;
    int k0 = blockIdx.y * 32;
#pragma unroll
    for (int j = 0; j < 4; j++) {
        int kk = ty + j * 8;
        t[kk][tx] = in[(size_t)(k0 + kk) * N + n0 + tx];
    }
    __syncthreads();
#pragma unroll
    for (int j = 0; j < 4; j++) {
        int a = ty + j * 8;
        float v = t[tx][a];
        __nv_bfloat16 h = __float2bfloat16(v);
        hiT[(size_t)(n0 + a) * K + k0 + tx] = h;
        loT[(size_t)(n0 + a) * K + k0 + tx] = __float2bfloat16(v - __bfloat162float(h));
    }
}

// ---------------------------------------------------------------------------
// fp32 SGEMM (delta GEMM only).  MODE 1: softplus(acc+bias).
// ---------------------------------------------------------------------------
template <int MODE>
__global__ __launch_bounds__(256)
void sgemm128(int M, int N, int K, int lda, int ldb, int ldc,
              const float* __restrict__ A, const float* __restrict__ B,
              float* __restrict__ C, const float* __restrict__ bias)
{
    const int BM = 128, BN = 128, BK = 8, TM = 8, TN = 8;
    __shared__ float As[BK][BM];
    __shared__ float Bs[BK][BN];

    const int tid = threadIdx.x;
    const int bx = blockIdx.x, by = blockIdx.y;

    const float* Ab = A + (size_t)by * BM * lda;
    const float* Bb = B + (size_t)bx * BN;

    const int aRow = tid >> 1;
    const int aCol = (tid & 1) * 4;
    const int bRow = tid >> 5;
    const int bCol = (tid & 31) * 4;
    const int tRow = (tid >> 4) * TM;
    const int tCol = (tid & 15) * TN;

    float acc[TM][TN];
#pragma unroll
    for (int i = 0; i < TM; i++)
#pragma unroll
        for (int j = 0; j < TN; j++) acc[i][j] = 0.f;

    for (int k0 = 0; k0 < K; k0 += BK) {
        float4 av = *(const float4*)(Ab + (size_t)aRow * lda + k0 + aCol);
        As[aCol + 0][aRow] = av.x;
        As[aCol + 1][aRow] = av.y;
        As[aCol + 2][aRow] = av.z;
        As[aCol + 3][aRow] = av.w;
        float4 bv = *(const float4*)(Bb + (size_t)(k0 + bRow) * ldb + bCol);
        *(float4*)&Bs[bRow][bCol] = bv;
        __syncthreads();

#pragma unroll
        for (int k = 0; k < BK; k++) {
            float4 a0 = *(const float4*)&As[k][tRow];
            float4 a1 = *(const float4*)&As[k][tRow + 4];
            float4 b0 = *(const float4*)&Bs[k][tCol];
            float4 b1 = *(const float4*)&Bs[k][tCol + 4];
            float ar[TM] = {a0.x, a0.y, a0.z, a0.w, a1.x, a1.y, a1.z, a1.w};
            float br[TN] = {b0.x, b0.y, b0.z, b0.w, b1.x, b1.y, b1.z, b1.w};
#pragma unroll
            for (int i = 0; i < TM; i++)
#pragma unroll
                for (int j = 0; j < TN; j++)
                    acc[i][j] += ar[i] * br[j];
        }
        __syncthreads();
    }

    float* Cb = C + (size_t)(by * BM) * ldc + bx * BN;
#pragma unroll
    for (int i = 0; i < TM; i++) {
        float v[TN];
#pragma unroll
        for (int j = 0; j < TN; j++) {
            float t = acc[i][j];
            if (MODE == 1) {
                t += bias[bx * BN + tCol + j];
                t = (t > 20.f) ? t : log1pf(expf(t));
            }
            v[j] = t;
        }
        *(float4*)(Cb + (size_t)(tRow + i) * ldc + tCol)     = make_float4(v[0], v[1], v[2], v[3]);
        *(float4*)(Cb + (size_t)(tRow + i) * ldc + tCol + 4) = make_float4(v[4], v[5], v[6], v[7]);
    }
}

// ---------------------------------------------------------------------------
// depthwise conv(4) + bias + silu, float4-vectorized over channels
// ---------------------------------------------------------------------------
__global__ __launch_bounds__(256)
void conv_silu_kernel(const float* __restrict__ xz,
                      const float* __restrict__ cw,
                      const float* __restrict__ cb,
                      float* __restrict__ u)
{
    int idx = blockIdx.x * blockDim.x + threadIdx.x;   // over M*DINNER/4
    if (idx >= MROWS * DINNER / 4) return;
    int d4  = (idx & (DINNER / 4 - 1)) * 4;            // channel base (mult of 4)
    int row = idx >> 9;                                // b*L + l
    int l   = row & (LL - 1);

    float4 w0 = *(const float4*)(cw + d4 * 4 + 0);     // weights d4+0: w0..w3
    float4 w1 = *(const float4*)(cw + d4 * 4 + 4);     // d4+1
    float4 w2 = *(const float4*)(cw + d4 * 4 + 8);     // d4+2
    float4 w3 = *(const float4*)(cw + d4 * 4 + 12);    // d4+3
    float4 bias = *(const float4*)(cb + d4);

    const float* base = xz + (size_t)row * (2 * DINNER) + d4;
    const int stride = 2 * DINNER;

    float4 s = bias;
    if (l >= 3) {
        float4 v = *(const float4*)(base - 3 * stride);
        s.x += v.x * w0.x; s.y += v.y * w1.x; s.z += v.z * w2.x; s.w += v.w * w3.x;
    }
    if (l >= 2) {
        float4 v = *(const float4*)(base - 2 * stride);
        s.x += v.x * w0.y; s.y += v.y * w1.y; s.z += v.z * w2.y; s.w += v.w * w3.y;
    }
    if (l >= 1) {
        float4 v = *(const float4*)(base - 1 * stride);
        s.x += v.x * w0.z; s.y += v.y * w1.z; s.z += v.z * w2.z; s.w += v.w * w3.z;
    }
    {
        float4 v = *(const float4*)(base);
        s.x += v.x * w0.w; s.y += v.y * w1.w; s.z += v.z * w2.w; s.w += v.w * w3.w;
    }
    float4 r;
    r.x = s.x / (1.f + expf(-s.x));
    r.y = s.y / (1.f + expf(-s.y));
    r.z = s.z / (1.f + expf(-s.z));
    r.w = s.w / (1.f + expf(-s.w));
    *(float4*)(u + (size_t)row * DINNER + d4) = r;
}

// ---------------------------------------------------------------------------
// xproj split-K:  part[ks] = u[:, ks*256:(ks+1)*256] @ W_xproj[ks*256.., :]
// Phase A: grid (KSPLITS, 32), block 256.  BM=64, KS=256, BK=32.
// Phase B: fixed-order reduce over KSPLITS.
// ---------------------------------------------------------------------------
__global__ __launch_bounds__(256)
void xprojA(const float* __restrict__ u, const float* __restrict__ W,
            float* __restrict__ part)
{
    __shared__ float As[64 * 32];      // [r][k], stride 32
    __shared__ float Bs[96 * 36];      // [c][k], stride 36

    const int ks = blockIdx.x;         // 0..7
    const int mb = blockIdx.y;         // 0..31
    const int tid = threadIdx.x;
    const int rg = tid >> 4;           // row group 0..15 -> rows rg*4..+3
    const int cg = tid & 15;           // cols j*16 + cg

    float acc[4][6];
#pragma unroll
    for (int r = 0; r < 4; r++)
#pragma unroll
        for (int j = 0; j < 6; j++) acc[r][j] = 0.f;

    for (int kc = 0; kc < 8; kc++) {
        const int kbase = ks * 256 + kc * 32;
#pragma unroll
        for (int i = tid; i < 64 * 32; i += 256) {
            int r = i >> 5, k = i & 31;
            As[r * 32 + k] = u[(size_t)(mb * 64 + r) * DINNER + kbase + k];
        }
#pragma unroll
        for (int i = tid; i < 96 * 32; i += 256) {
            int c = i % 96, k = i / 96;
            Bs[c * 36 + k] = W[(size_t)(kbase + k) * XPROJ_N + c];
        }
        __syncthreads();
#pragma unroll
        for (int kq = 0; kq < 8; kq++) {
            float4 a[4], b[6];
#pragma unroll
            for (int r = 0; r < 4; r++)
                a[r] = *(const float4*)&As[(rg * 4 + r) * 32 + kq * 4];
#pragma unroll
            for (int j = 0; j < 6; j++)
                b[j] = *(const float4*)&Bs[(j * 16 + cg) * 36 + kq * 4];
#pragma unroll
            for (int r = 0; r < 4; r++)
#pragma unroll
                for (int j = 0; j < 6; j++)
                    acc[r][j] += a[r].x * b[j].x + a[r].y * b[j].y
                               + a[r].z * b[j].z + a[r].w * b[j].w;
        }
        __syncthreads();
    }
#pragma unroll
    for (int r = 0; r < 4; r++)
#pragma unroll
        for (int j = 0; j < 6; j++)
            part[((size_t)ks * MROWS + mb * 64 + rg * 4 + r) * XPROJ_N + j * 16 + cg]
                = acc[r][j];
}

__global__ __launch_bounds__(256)
void xprojB(const float* __restrict__ part, float* __restrict__ xdbl)
{
    int idx = blockIdx.x * 256 + threadIdx.x;     // < MROWS*XPROJ_N
    if (idx >= MROWS * XPROJ_N) return;
    float s = 0.f;
#pragma unroll
    for (int ks = 0; ks < KSPLITS; ks++)
        s += part[(size_t)ks * MROWS * XPROJ_N + idx];
    xdbl[idx] = s;
}

// ---------------------------------------------------------------------------
// selective scan (emits y as bf16 hi/lo split directly)
// ---------------------------------------------------------------------------
#define SCAN_CT 64
__global__ __launch_bounds__(256)
void scan_kernel(const float* __restrict__ delta,
                 const float* __restrict__ u,
                 const float* __restrict__ xz,
                 const float* __restrict__ xdbl,
                 const float* __restrict__ A_log,
                 const float* __restrict__ Dskip,
                 __nv_bfloat16* __restrict__ yh,
                 __nv_bfloat16* __restrict__ yl)
{
    __shared__ float sDelta[SCAN_CT][16];
    __shared__ float sU[SCAN_CT][16];
    __shared__ float sZ[SCAN_CT][16];
    __shared__ float sB[SCAN_CT][16];
    __shared__ float sC[SCAN_CT][16];
    __shared__ float sY[SCAN_CT][16];

    const int tid = threadIdx.x;
    const int tn = tid & 15;
    const int td = tid >> 4;
    const int dbase = blockIdx.x * 16;
    const int d = dbase + td;
    const int b = blockIdx.y;

    const float Aq  = -expf(A_log[d * DSTATE + tn]);
    const float dsk = Dskip[d];

    float h = 0.f;

    for (int t0 = 0; t0 < LL; t0 += SCAN_CT) {
#pragma unroll
        for (int i = tid; i < SCAN_CT * 16; i += 256) {
            int r = i >> 4, c = i & 15;
            int row = b * LL + t0 + r;
            sDelta[r][c] = delta[(size_t)row * DINNER + dbase + c];
            sU[r][c]     = u[(size_t)row * DINNER + dbase + c];
            sZ[r][c]     = xz[(size_t)row * (2 * DINNER) + DINNER + dbase + c];
            sB[r][c]     = xdbl[(size_t)row * XPROJ_N + DTRANK + c];
            sC[r][c]     = xdbl[(size_t)row * XPROJ_N + DTRANK + DSTATE + c];
        }
        __syncthreads();

#pragma unroll 4
        for (int tt = 0; tt < SCAN_CT; tt++) {
            float dlt = sDelta[tt][td];
            float uu  = sU[tt][td];
            float bb  = sB[tt][tn];
            float cc  = sC[tt][tn];
            float dA  = __expf(dlt * Aq);
            h = dA * h + (dlt * uu) * bb;
            float p = h * cc;
            p += __shfl_xor_sync(0xffffffffu, p, 8);
            p += __shfl_xor_sync(0xffffffffu, p, 4);
            p += __shfl_xor_sync(0xffffffffu, p, 2);
            p += __shfl_xor_sync(0xffffffffu, p, 1);
            if (tn == 0) {
                float zz = sZ[tt][td];
                float yv = p + dsk * uu;
                yv *= zz / (1.f + expf(-zz));
                sY[tt][td] = yv;
            }
        }
        __syncthreads();

#pragma unroll
        for (int i = tid; i < SCAN_CT * 16; i += 256) {
            int r = i >> 4, c = i & 15;
            int row = b * LL + t0 + r;
            float v = sY[r][c];
            __nv_bfloat16 hb = __float2bfloat16(v);
            yh[(size_t)row * DINNER + dbase + c] = hb;
            yl[(size_t)row * DINNER + dbase + c] =
                __float2bfloat16(v - __bfloat162float(hb));
        }
        __syncthreads();
    }
}

// ---------------------------------------------------------------------------
extern "C" void kernel_launch(void* const* d_in, const int* in_sizes, int n_in,
                              void* d_out, int out_size)
{
    const float* x       = (const float*)d_in[0];  // [2,1024,1024]
    const float* W_in    = (const float*)d_in[1];  // [1024, 4096]
    const float* conv_w  = (const float*)d_in[2];  // [2048, 1, 4]
    const float* conv_b  = (const float*)d_in[3];  // [2048]
    const float* W_xproj = (const float*)d_in[4];  // [2048, 96]
    const float* W_dt    = (const float*)d_in[5];  // [64, 2048]
    const float* b_dt    = (const float*)d_in[6];  // [2048]
    const float* A_log   = (const float*)d_in[7];  // [2048, 16]
    const float* D_skip  = (const float*)d_in[8];  // [2048]
    const float* W_out   = (const float*)d_in[9];  // [2048, 1024]
    float* out = (float*)d_out;                    // [2,1024,1024]

    float* xz;    cudaGetSymbolAddress((void**)&xz,    g_xz);
    float* u;     cudaGetSymbolAddress((void**)&u,     g_u);
    float* xdbl;  cudaGetSymbolAddress((void**)&xdbl,  g_xdbl);
    float* delta; cudaGetSymbolAddress((void**)&delta, g_delta);
    float* xpart; cudaGetSymbolAddress((void**)&xpart, g_xpart);

    __nv_bfloat16 *xh, *xl, *winTh, *winTl, *yh, *yl, *woutTh, *woutTl;
    cudaGetSymbolAddress((void**)&xh,     g_xh);
    cudaGetSymbolAddress((void**)&xl,     g_xl);
    cudaGetSymbolAddress((void**)&winTh,  g_winT_h);
    cudaGetSymbolAddress((void**)&winTl,  g_winT_l);
    cudaGetSymbolAddress((void**)&yh,     g_yh);
    cudaGetSymbolAddress((void**)&yl,     g_yl);
    cudaGetSymbolAddress((void**)&woutTh, g_woutT_h);
    cudaGetSymbolAddress((void**)&woutTl, g_woutT_l);

    cudaFuncSetAttribute(gemm_mma, cudaFuncAttributeMaxDynamicSharedMemorySize, GM_SMEM);

    // operand conversions
    split_fp32_bf16<<<(MROWS * DMODEL) / 256, 256>>>(x, xh, xl, MROWS * DMODEL);
    tsplit_fp32_bf16<<<dim3(4096 / 32, DMODEL / 32), 256>>>(W_in, winTh, winTl, DMODEL, 4096);
    tsplit_fp32_bf16<<<dim3(DMODEL / 32, DINNER / 32), 256>>>(W_out, woutTh, woutTl, DINNER, DMODEL);

    // 1) xz = x @ W_in        [2048,1024] @ [1024,4096]   (tensor cores)
    gemm_mma<<<dim3(4096 / 128, MROWS / 128), 512, GM_SMEM>>>(
        xh, xl, winTh, winTl, xz, DMODEL, 4096);

    // 2) u = silu(conv(xz[:, :2048]) + conv_b)
    conv_silu_kernel<<<(MROWS * DINNER / 4 + 255) / 256, 256>>>(xz, conv_w, conv_b, u);

    // 3) xdbl = u @ W_xproj   (deterministic split-K)
    xprojA<<<dim3(KSPLITS, MROWS / 64), 256>>>(u, W_xproj, xpart);
    xprojB<<<(MROWS * XPROJ_N + 255) / 256, 256>>>(xpart, xdbl);

    // 4) delta = softplus(xdbl[:, :64] @ W_dt + b_dt)
    sgemm128<1><<<dim3(DINNER / 128, MROWS / 128), 256>>>(
        MROWS, DINNER, DTRANK, XPROJ_N, DINNER, DINNER, xdbl, W_dt, delta, b_dt);

    // 5) selective scan -> yh/yl (bf16 split, feeds GEMM4 directly)
    scan_kernel<<<dim3(DINNER / 16, BB), 256>>>(delta, u, xz, xdbl, A_log, D_skip, yh, yl);

    // 6) out = y @ W_out      [2048,2048] @ [2048,1024]   (tensor cores)
    gemm_mma<<<dim3(1024 / 128, MROWS / 128), 512, GM_SMEM>>>(
        yh, yl, woutTh, woutTl, out, DINNER, 1024);
}

// round 7
// speedup vs baseline: 1.9340x; 1.0067x over previous
#include <cuda_runtime.h>
#include <cuda_bf16.h>
#include <math.h>
#include <cstdint>

// ---------------------------------------------------------------------------
// TemporalMamba: B=2, L=1024, D_MODEL=1024, D_INNER=2048, D_STATE=16,
// D_CONV=4, DT_RANK=64.
// Tensor cores via mma.sync.m16n8k16 bf16x3 split (toolchain is compute_100
// base: tcgen05 unavailable).
// ---------------------------------------------------------------------------

#define BB       2
#define LL       1024
#define DMODEL   1024
#define DINNER   2048
#define DSTATE   16
#define DTRANK   64
#define MROWS    (BB * LL)                  // 2048
#define XPROJ_N  (DTRANK + 2 * DSTATE)      // 96
#define KSPLITS  8

// ------------------------- scratch (device globals) ------------------------
__device__ float g_xz[MROWS * 2 * DINNER];      // [M, 4096]
__device__ float g_u[MROWS * DINNER];           // [M, 2048]
__device__ float g_xdbl[MROWS * XPROJ_N];       // [M, 96]
__device__ float g_xpart[KSPLITS * MROWS * XPROJ_N];  // xproj split-K partials
__device__ float g_part[2 * MROWS * DMODEL];    // GEMM4 split-K partials (16MB)

// bf16 split operands
__device__ __nv_bfloat16 g_xh[MROWS * DMODEL];
__device__ __nv_bfloat16 g_xl[MROWS * DMODEL];
__device__ __nv_bfloat16 g_winT_h[4096 * DMODEL];
__device__ __nv_bfloat16 g_winT_l[4096 * DMODEL];
__device__ __nv_bfloat16 g_yh[MROWS * DINNER];
__device__ __nv_bfloat16 g_yl[MROWS * DINNER];
__device__ __nv_bfloat16 g_woutT_h[DMODEL * DINNER];
__device__ __nv_bfloat16 g_woutT_l[DMODEL * DINNER];

// ---------------------------------------------------------------------------
// mma.sync / ldmatrix / cp.async helpers
// ---------------------------------------------------------------------------
__device__ __forceinline__ uint32_t smem_u32(const void* p) {
    uint32_t a;
    asm("{ .reg .u64 t; cvta.to.shared.u64 t, %1; cvt.u32.u64 %0, t; }" : "=r"(a) : "l"(p));
    return a;
}
__device__ __forceinline__ void cpa16(uint32_t s, const void* g) {
    asm volatile("cp.async.cg.shared.global [%0], [%1], 16;" :: "r"(s), "l"(g));
}
__device__ __forceinline__ void ldsm4(uint32_t& r0, uint32_t& r1, uint32_t& r2, uint32_t& r3,
                                      uint32_t addr) {
    asm volatile("ldmatrix.sync.aligned.m8n8.x4.shared.b16 {%0,%1,%2,%3}, [%4];"
                 : "=r"(r0), "=r"(r1), "=r"(r2), "=r"(r3) : "r"(addr));
}
__device__ __forceinline__ void mma16816(float& c0, float& c1, float& c2, float& c3,
                                         uint32_t a0, uint32_t a1, uint32_t a2, uint32_t a3,
                                         uint32_t b0, uint32_t b1) {
    asm volatile(
        "mma.sync.aligned.m16n8k16.row.col.f32.bf16.bf16.f32 "
        "{%0,%1,%2,%3}, {%4,%5,%6,%7}, {%8,%9}, {%0,%1,%2,%3};"
        : "+f"(c0), "+f"(c1), "+f"(c2), "+f"(c3)
        : "r"(a0), "r"(a1), "r"(a2), "r"(a3), "r"(b0), "r"(b1));
}

// ---------------------------------------------------------------------------
// bf16x3 split tensor-core GEMM:  C[M,N] = (Ah+Al)[M,K] @ (Bh+Bl)^T
//   A row-major [M][K], B as Bt[N][K] (K-major).  CTA: 256 thr = 8 warps
//   (2 M x 4 N), tile 128x128, warp tile 64x32, BK=64, cp.async double
//   buffer.  Terms: AhBh + AhBl + AlBh, fp32 accumulate.
//   gridDim.z splits K deterministically; partial z writes C + z*partStride.
// ---------------------------------------------------------------------------
#define SSTR     72                                  // smem row stride (bf16)
#define TILE_B   (128 * SSTR * 2)                    // 18432 B per tile
#define STAGE_B  (4 * TILE_B)                        // Ah, Al, Bh, Bl
#define GM_SMEM  (2 * STAGE_B)                       // 147456 B

__device__ __forceinline__ void load_stage_tile(
    const __nv_bfloat16* __restrict__ G, int rowBase, int k0, int K,
    uint32_t sdst, int tid)
{
#pragma unroll
    for (int i = 0; i < 4; i++) {
        int idx = tid + i * 256;            // 0..1023
        int r = idx >> 3;                   // row 0..127
        int q = idx & 7;                    // 16B chunk in row
        const void* g = G + (size_t)(rowBase + r) * K + k0 + q * 8;
        cpa16(sdst + (uint32_t)(r * SSTR + q * 8) * 2, g);
    }
}

__global__ __launch_bounds__(256, 1)
void gemm_mma(const __nv_bfloat16* __restrict__ Ah, const __nv_bfloat16* __restrict__ Al,
              const __nv_bfloat16* __restrict__ Bh, const __nv_bfloat16* __restrict__ Bl,
              float* __restrict__ C, int Kfull, int ldc, int kdepth,
              size_t partStride)
{
    extern __shared__ __align__(16) char dsm[];
    const uint32_t sbase = smem_u32(dsm);

    const int tid  = threadIdx.x;
    const int wid  = tid >> 5;
    const int lane = tid & 31;
    const int wm   = wid >> 2;              // 0..1  (M)
    const int wn   = wid & 3;               // 0..3  (N)
    const int bx   = blockIdx.x, by = blockIdx.y;
    const int kbase = blockIdx.z * kdepth;
    C += (size_t)blockIdx.z * partStride;

    const int aRow  = lane & 15;
    const int aCsel = (lane >> 4) * 8;
    const int bRow  = (lane & 7) + ((lane >> 4) << 3);
    const int bCsel = ((lane >> 3) & 1) * 8;

    float acc[4][4][4];
#pragma unroll
    for (int i = 0; i < 4; i++)
#pragma unroll
        for (int j = 0; j < 4; j++)
#pragma unroll
            for (int v = 0; v < 4; v++) acc[i][j][v] = 0.f;

    const int NC = kdepth >> 6;

    load_stage_tile(Ah, by * 128, kbase, Kfull, sbase + 0 * TILE_B, tid);
    load_stage_tile(Al, by * 128, kbase, Kfull, sbase + 1 * TILE_B, tid);
    load_stage_tile(Bh, bx * 128, kbase, Kfull, sbase + 2 * TILE_B, tid);
    load_stage_tile(Bl, bx * 128, kbase, Kfull, sbase + 3 * TILE_B, tid);
    asm volatile("cp.async.commit_group;");

    for (int c = 0; c < NC; c++) {
        if (c + 1 < NC) {
            const uint32_t sd = sbase + ((c + 1) & 1) * STAGE_B;
            const int k0 = kbase + ((c + 1) << 6);
            load_stage_tile(Ah, by * 128, k0, Kfull, sd + 0 * TILE_B, tid);
            load_stage_tile(Al, by * 128, k0, Kfull, sd + 1 * TILE_B, tid);
            load_stage_tile(Bh, bx * 128, k0, Kfull, sd + 2 * TILE_B, tid);
            load_stage_tile(Bl, bx * 128, k0, Kfull, sd + 3 * TILE_B, tid);
            asm volatile("cp.async.commit_group;");
            asm volatile("cp.async.wait_group 1;");
        } else {
            asm volatile("cp.async.wait_group 0;");
        }
        __syncthreads();

        const uint32_t st = sbase + (c & 1) * STAGE_B;
        const uint32_t sAh = st + 0 * TILE_B;
        const uint32_t sAl = st + 1 * TILE_B;
        const uint32_t sBh = st + 2 * TILE_B;
        const uint32_t sBl = st + 3 * TILE_B;

#pragma unroll
        for (int kk = 0; kk < 64; kk += 16) {
            uint32_t ah[4][4], al[4][4], bh[2][4], bl[2][4];
#pragma unroll
            for (int i = 0; i < 4; i++) {
                uint32_t off = (uint32_t)((wm * 64 + i * 16 + aRow) * SSTR + kk + aCsel) * 2;
                ldsm4(ah[i][0], ah[i][1], ah[i][2], ah[i][3], sAh + off);
            }
#pragma unroll
            for (int j2 = 0; j2 < 2; j2++) {
                uint32_t off = (uint32_t)((wn * 32 + j2 * 16 + bRow) * SSTR + kk + bCsel) * 2;
                ldsm4(bh[j2][0], bh[j2][1], bh[j2][2], bh[j2][3], sBh + off);
            }
            // hh
#pragma unroll
            for (int i = 0; i < 4; i++)
#pragma unroll
                for (int j = 0; j < 4; j++) {
                    const uint32_t* b = bh[j >> 1] + (j & 1) * 2;
                    mma16816(acc[i][j][0], acc[i][j][1], acc[i][j][2], acc[i][j][3],
                             ah[i][0], ah[i][1], ah[i][2], ah[i][3], b[0], b[1]);
                }
            // hl
#pragma unroll
            for (int j2 = 0; j2 < 2; j2++) {
                uint32_t off = (uint32_t)((wn * 32 + j2 * 16 + bRow) * SSTR + kk + bCsel) * 2;
                ldsm4(bl[j2][0], bl[j2][1], bl[j2][2], bl[j2][3], sBl + off);
            }
#pragma unroll
            for (int i = 0; i < 4; i++)
#pragma unroll
                for (int j = 0; j < 4; j++) {
                    const uint32_t* b = bl[j >> 1] + (j & 1) * 2;
                    mma16816(acc[i][j][0], acc[i][j][1], acc[i][j][2], acc[i][j][3],
                             ah[i][0], ah[i][1], ah[i][2], ah[i][3], b[0], b[1]);
                }
            // lh
#pragma unroll
            for (int i = 0; i < 4; i++) {
                uint32_t off = (uint32_t)((wm * 64 + i * 16 + aRow) * SSTR + kk + aCsel) * 2;
                ldsm4(al[i][0], al[i][1], al[i][2], al[i][3], sAl + off);
            }
#pragma unroll
            for (int i = 0; i < 4; i++)
#pragma unroll
                for (int j = 0; j < 4; j++) {
                    const uint32_t* b = bh[j >> 1] + (j & 1) * 2;
                    mma16816(acc[i][j][0], acc[i][j][1], acc[i][j][2], acc[i][j][3],
                             al[i][0], al[i][1], al[i][2], al[i][3], b[0], b[1]);
                }
        }
        __syncthreads();
    }

    const int mBase = by * 128 + wm * 64;
    const int nBase = bx * 128 + wn * 32;
    const int r0 = lane >> 2;
    const int c0 = (lane & 3) * 2;
#pragma unroll
    for (int i = 0; i < 4; i++) {
#pragma unroll
        for (int j = 0; j < 4; j++) {
            float* p0 = C + (size_t)(mBase + i * 16 + r0) * ldc + nBase + j * 8 + c0;
            *(float2*)p0                     = make_float2(acc[i][j][0], acc[i][j][1]);
            *(float2*)(p0 + (size_t)8 * ldc) = make_float2(acc[i][j][2], acc[i][j][3]);
        }
    }
}

// fixed-order split-K reduce: out = part[0..n) + part[n..2n)  (float4)
__global__ __launch_bounds__(256)
void reduce2(const float* __restrict__ part, float* __restrict__ out, int n)
{
    int i = (blockIdx.x * 256 + threadIdx.x) * 4;
    if (i >= n) return;
    float4 a = *(const float4*)(part + i);
    float4 b = *(const float4*)(part + (size_t)n + i);
    float4 r = make_float4(a.x + b.x, a.y + b.y, a.z + b.z, a.w + b.w);
    *(float4*)(out + i) = r;
}

// ---------------------------------------------------------------------------
// fp32 -> bf16 hi/lo split (row-major)
// ---------------------------------------------------------------------------
__global__ __launch_bounds__(256)
void split_fp32_bf16(const float* __restrict__ in, __nv_bfloat16* __restrict__ hi,
                     __nv_bfloat16* __restrict__ lo, int n)
{
    int i = blockIdx.x * 256 + threadIdx.x;
    if (i >= n) return;
    float a = in[i];
    __nv_bfloat16 h = __float2bfloat16(a);
    hi[i] = h;
    lo[i] = __float2bfloat16(a - __bfloat162float(h));
}

// transpose + split:  in[K][N] fp32  ->  hiT/loT [N][K] bf16
__global__ __launch_bounds__(256)
void tsplit_fp32_bf16(const float* __restrict__ in,
                      __nv_bfloat16* __restrict__ hiT, __nv_bfloat16* __restrict__ loT,
                      int K, int N)
{
    __shared__ float t[32][33];
    int tx = threadIdx.x & 31;
    int ty = threadIdx.x >> 5;
    int n0 = blockIdx.x * 32;
    int k0 = blockIdx.y * 32;
#pragma unroll
    for (int j = 0; j < 4; j++) {
        int kk = ty + j * 8;
        t[kk][tx] = in[(size_t)(k0 + kk) * N + n0 + tx];
    }
    __syncthreads();
#pragma unroll
    for (int j = 0; j < 4; j++) {
        int a = ty + j * 8;
        float v = t[tx][a];
        __nv_bfloat16 h = __float2bfloat16(v);
        hiT[(size_t)(n0 + a) * K + k0 + tx] = h;
        loT[(size_t)(n0 + a) * K + k0 + tx] = __float2bfloat16(v - __bfloat162float(h));
    }
}

// ---------------------------------------------------------------------------
// depthwise conv(4) + bias + silu, float4-vectorized over channels
// ---------------------------------------------------------------------------
__global__ __launch_bounds__(256)
void conv_silu_kernel(const float* __restrict__ xz,
                      const float* __restrict__ cw,
                      const float* __restrict__ cb,
                      float* __restrict__ u)
{
    int idx = blockIdx.x * blockDim.x + threadIdx.x;   // over M*DINNER/4
    if (idx >= MROWS * DINNER / 4) return;
    int d4  = (idx & (DINNER / 4 - 1)) * 4;
    int row = idx >> 9;
    int l   = row & (LL - 1);

    float4 w0 = *(const float4*)(cw + d4 * 4 + 0);
    float4 w1 = *(const float4*)(cw + d4 * 4 + 4);
    float4 w2 = *(const float4*)(cw + d4 * 4 + 8);
    float4 w3 = *(const float4*)(cw + d4 * 4 + 12);
    float4 bias = *(const float4*)(cb + d4);

    const float* base = xz + (size_t)row * (2 * DINNER) + d4;
    const int stride = 2 * DINNER;

    float4 s = bias;
    if (l >= 3) {
        float4 v = *(const float4*)(base - 3 * stride);
        s.x += v.x * w0.x; s.y += v.y * w1.x; s.z += v.z * w2.x; s.w += v.w * w3.x;
    }
    if (l >= 2) {
        float4 v = *(const float4*)(base - 2 * stride);
        s.x += v.x * w0.y; s.y += v.y * w1.y; s.z += v.z * w2.y; s.w += v.w * w3.y;
    }
    if (l >= 1) {
        float4 v = *(const float4*)(base - 1 * stride);
        s.x += v.x * w0.z; s.y += v.y * w1.z; s.z += v.z * w2.z; s.w += v.w * w3.z;
    }
    {
        float4 v = *(const float4*)(base);
        s.x += v.x * w0.w; s.y += v.y * w1.w; s.z += v.z * w2.w; s.w += v.w * w3.w;
    }
    float4 r;
    r.x = s.x / (1.f + expf(-s.x));
    r.y = s.y / (1.f + expf(-s.y));
    r.z = s.z / (1.f + expf(-s.z));
    r.w = s.w / (1.f + expf(-s.w));
    *(float4*)(u + (size_t)row * DINNER + d4) = r;
}

// ---------------------------------------------------------------------------
// xproj split-K:  part[ks] = u[:, ks*256:(ks+1)*256] @ W_xproj[ks*256.., :]
// ---------------------------------------------------------------------------
__global__ __launch_bounds__(256)
void xprojA(const float* __restrict__ u, const float* __restrict__ W,
            float* __restrict__ part)
{
    __shared__ float As[64 * 32];      // [r][k], stride 32
    __shared__ float Bs[96 * 36];      // [c][k], stride 36

    const int ks = blockIdx.x;
    const int mb = blockIdx.y;
    const int tid = threadIdx.x;
    const int rg = tid >> 4;
    const int cg = tid & 15;

    float acc[4][6];
#pragma unroll
    for (int r = 0; r < 4; r++)
#pragma unroll
        for (int j = 0; j < 6; j++) acc[r][j] = 0.f;

    for (int kc = 0; kc < 8; kc++) {
        const int kbase = ks * 256 + kc * 32;
#pragma unroll
        for (int i = tid; i < 64 * 32; i += 256) {
            int r = i >> 5, k = i & 31;
            As[r * 32 + k] = u[(size_t)(mb * 64 + r) * DINNER + kbase + k];
        }
#pragma unroll
        for (int i = tid; i < 96 * 32; i += 256) {
            int c = i % 96, k = i / 96;
            Bs[c * 36 + k] = W[(size_t)(kbase + k) * XPROJ_N + c];
        }
        __syncthreads();
#pragma unroll
        for (int kq = 0; kq < 8; kq++) {
            float4 a[4], b[6];
#pragma unroll
            for (int r = 0; r < 4; r++)
                a[r] = *(const float4*)&As[(rg * 4 + r) * 32 + kq * 4];
#pragma unroll
            for (int j = 0; j < 6; j++)
                b[j] = *(const float4*)&Bs[(j * 16 + cg) * 36 + kq * 4];
#pragma unroll
            for (int r = 0; r < 4; r++)
#pragma unroll
                for (int j = 0; j < 6; j++)
                    acc[r][j] += a[r].x * b[j].x + a[r].y * b[j].y
                               + a[r].z * b[j].z + a[r].w * b[j].w;
        }
        __syncthreads();
    }
#pragma unroll
    for (int r = 0; r < 4; r++)
#pragma unroll
        for (int j = 0; j < 6; j++)
            part[((size_t)ks * MROWS + mb * 64 + rg * 4 + r) * XPROJ_N + j * 16 + cg]
                = acc[r][j];
}

__global__ __launch_bounds__(256)
void xprojB(const float* __restrict__ part, float* __restrict__ xdbl)
{
    int idx = blockIdx.x * 256 + threadIdx.x;
    if (idx >= MROWS * XPROJ_N) return;
    float s = 0.f;
#pragma unroll
    for (int ks = 0; ks < KSPLITS; ks++)
        s += part[(size_t)ks * MROWS * XPROJ_N + idx];
    xdbl[idx] = s;
}

// ---------------------------------------------------------------------------
// selective scan with fused delta GEMM (dt_lr @ W_dt + b_dt -> softplus)
// and fused y -> bf16 hi/lo split output.
// ---------------------------------------------------------------------------
#define SCAN_CT 64
__global__ __launch_bounds__(256)
void scan_kernel(const float* __restrict__ u,
                 const float* __restrict__ xz,
                 const float* __restrict__ xdbl,
                 const float* __restrict__ W_dt,   // [64, 2048]
                 const float* __restrict__ b_dt,   // [2048]
                 const float* __restrict__ A_log,
                 const float* __restrict__ Dskip,
                 __nv_bfloat16* __restrict__ yh,
                 __nv_bfloat16* __restrict__ yl)
{
    __shared__ float sDT[SCAN_CT][64];   // dt_lr rows (xdbl[:, :64])
    __shared__ float sW[64][16];         // W_dt[:, dbase..dbase+16)
    __shared__ float sbd[16];
    __shared__ float sDelta[SCAN_CT][16];
    __shared__ float sU[SCAN_CT][16];
    __shared__ float sZ[SCAN_CT][16];
    __shared__ float sB[SCAN_CT][16];
    __shared__ float sC[SCAN_CT][16];
    __shared__ float sY[SCAN_CT][16];

    const int tid = threadIdx.x;
    const int tn = tid & 15;
    const int td = tid >> 4;
    const int dbase = blockIdx.x * 16;
    const int d = dbase + td;
    const int b = blockIdx.y;

    // load W_dt slice + bias once
    for (int i = tid; i < 64 * 16; i += 256) {
        int r = i >> 4, c = i & 15;
        sW[r][c] = W_dt[(size_t)r * DINNER + dbase + c];
    }
    if (tid < 16) sbd[tid] = b_dt[dbase + tid];

    const float Aq  = -expf(A_log[d * DSTATE + tn]);
    const float dsk = Dskip[d];

    float h = 0.f;

    for (int t0 = 0; t0 < LL; t0 += SCAN_CT) {
        // stage tiles
#pragma unroll
        for (int i = tid; i < SCAN_CT * 16; i += 256) {
            int r = i >> 4, c = i & 15;
            int row = b * LL + t0 + r;
            sU[r][c] = u[(size_t)row * DINNER + dbase + c];
            sZ[r][c] = xz[(size_t)row * (2 * DINNER) + DINNER + dbase + c];
            sB[r][c] = xdbl[(size_t)row * XPROJ_N + DTRANK + c];
            sC[r][c] = xdbl[(size_t)row * XPROJ_N + DTRANK + DSTATE + c];
        }
#pragma unroll
        for (int i = tid; i < SCAN_CT * 64; i += 256) {
            int r = i >> 6, k = i & 63;
            int row = b * LL + t0 + r;
            sDT[r][k] = xdbl[(size_t)row * XPROJ_N + k];
        }
        __syncthreads();

        // fused delta: sDelta[r][c] = softplus(sum_k sDT[r][k]*sW[k][c] + sbd[c])
        {
            float sv[4];
            int rr[4], cc[4];
#pragma unroll
            for (int v = 0; v < 4; v++) {
                int idx = tid + v * 256;
                rr[v] = idx >> 4;
                cc[v] = idx & 15;
                sv[v] = sbd[cc[v]];
            }
#pragma unroll 8
            for (int k = 0; k < 64; k++) {
#pragma unroll
                for (int v = 0; v < 4; v++)
                    sv[v] += sDT[rr[v]][k] * sW[k][cc[v]];
            }
#pragma unroll
            for (int v = 0; v < 4; v++) {
                float t = sv[v];
                sDelta[rr[v]][cc[v]] = (t > 20.f) ? t : log1pf(expf(t));
            }
        }
        __syncthreads();

#pragma unroll 4
        for (int tt = 0; tt < SCAN_CT; tt++) {
            float dlt = sDelta[tt][td];
            float uu  = sU[tt][td];
            float bb  = sB[tt][tn];
            float cc  = sC[tt][tn];
            float dA  = __expf(dlt * Aq);
            h = dA * h + (dlt * uu) * bb;
            float p = h * cc;
            p += __shfl_xor_sync(0xffffffffu, p, 8);
            p += __shfl_xor_sync(0xffffffffu, p, 4);
            p += __shfl_xor_sync(0xffffffffu, p, 2);
            p += __shfl_xor_sync(0xffffffffu, p, 1);
            if (tn == 0) {
                float zz = sZ[tt][td];
                float yv = p + dsk * uu;
                yv *= zz / (1.f + expf(-zz));
                sY[tt][td] = yv;
            }
        }
        __syncthreads();

#pragma unroll
        for (int i = tid; i < SCAN_CT * 16; i += 256) {
            int r = i >> 4, c = i & 15;
            int row = b * LL + t0 + r;
            float v = sY[r][c];
            __nv_bfloat16 hb = __float2bfloat16(v);
            yh[(size_t)row * DINNER + dbase + c] = hb;
            yl[(size_t)row * DINNER + dbase + c] =
                __float2bfloat16(v - __bfloat162float(hb));
        }
        __syncthreads();
    }
}

// ---------------------------------------------------------------------------
extern "C" void kernel_launch(void* const* d_in, const int* in_sizes, int n_in,
                              void* d_out, int out_size)
{
    const float* x       = (const float*)d_in[0];  // [2,1024,1024]
    const float* W_in    = (const float*)d_in[1];  // [1024, 4096]
    const float* conv_w  = (const float*)d_in[2];  // [2048, 1, 4]
    const float* conv_b  = (const float*)d_in[3];  // [2048]
    const float* W_xproj = (const float*)d_in[4];  // [2048, 96]
    const float* W_dt    = (const float*)d_in[5];  // [64, 2048]
    const float* b_dt    = (const float*)d_in[6];  // [2048]
    const float* A_log   = (const float*)d_in[7];  // [2048, 16]
    const float* D_skip  = (const float*)d_in[8];  // [2048]
    const float* W_out   = (const float*)d_in[9];  // [2048, 1024]
    float* out = (float*)d_out;                    // [2,1024,1024]

    float* xz;    cudaGetSymbolAddress((void**)&xz,    g_xz);
    float* u;     cudaGetSymbolAddress((void**)&u,     g_u);
    float* xdbl;  cudaGetSymbolAddress((void**)&xdbl,  g_xdbl);
    float* xpart; cudaGetSymbolAddress((void**)&xpart, g_xpart);
    float* part;  cudaGetSymbolAddress((void**)&part,  g_part);

    __nv_bfloat16 *xh, *xl, *winTh, *winTl, *yh, *yl, *woutTh, *woutTl;
    cudaGetSymbolAddress((void**)&xh,     g_xh);
    cudaGetSymbolAddress((void**)&xl,     g_xl);
    cudaGetSymbolAddress((void**)&winTh,  g_winT_h);
    cudaGetSymbolAddress((void**)&winTl,  g_winT_l);
    cudaGetSymbolAddress((void**)&yh,     g_yh);
    cudaGetSymbolAddress((void**)&yl,     g_yl);
    cudaGetSymbolAddress((void**)&woutTh, g_woutT_h);
    cudaGetSymbolAddress((void**)&woutTl, g_woutT_l);

    cudaFuncSetAttribute(gemm_mma, cudaFuncAttributeMaxDynamicSharedMemorySize, GM_SMEM);

    // operand conversions
    split_fp32_bf16<<<(MROWS * DMODEL) / 256, 256>>>(x, xh, xl, MROWS * DMODEL);
    tsplit_fp32_bf16<<<dim3(4096 / 32, DMODEL / 32), 256>>>(W_in, winTh, winTl, DMODEL, 4096);
    tsplit_fp32_bf16<<<dim3(DMODEL / 32, DINNER / 32), 256>>>(W_out, woutTh, woutTl, DINNER, DMODEL);

    // 1) xz = x @ W_in        [2048,1024] @ [1024,4096]   (tensor cores)
    gemm_mma<<<dim3(4096 / 128, MROWS / 128, 1), 256, GM_SMEM>>>(
        xh, xl, winTh, winTl, xz, DMODEL, 4096, DMODEL, 0);

    // 2) u = silu(conv(xz[:, :2048]) + conv_b)
    conv_silu_kernel<<<(MROWS * DINNER / 4 + 255) / 256, 256>>>(xz, conv_w, conv_b, u);

    // 3) xdbl = u @ W_xproj   (deterministic split-K)
    xprojA<<<dim3(KSPLITS, MROWS / 64), 256>>>(u, W_xproj, xpart);
    xprojB<<<(MROWS * XPROJ_N + 255) / 256, 256>>>(xpart, xdbl);

    // 4+5) fused delta + selective scan -> yh/yl (bf16 split)
    scan_kernel<<<dim3(DINNER / 16, BB), 256>>>(u, xz, xdbl, W_dt, b_dt,
                                                A_log, D_skip, yh, yl);

    // 6) out = y @ W_out   [2048,2048]@[2048,1024], 2-way split-K + reduce
    gemm_mma<<<dim3(1024 / 128, MROWS / 128, 2), 256, GM_SMEM>>>(
        yh, yl, woutTh, woutTl, part, DINNER, 1024, 1024,
        (size_t)MROWS * DMODEL);
    reduce2<<<(MROWS * DMODEL / 4 + 255) / 256, 256>>>(part, out, MROWS * DMODEL);
}

// round 8
// speedup vs baseline: 2.4955x; 1.2903x over previous
#include <cuda_runtime.h>
#include <cuda_bf16.h>
#include <math.h>
#include <cstdint>

// ---------------------------------------------------------------------------
// TemporalMamba: B=2, L=1024, D_MODEL=1024, D_INNER=2048, D_STATE=16,
// D_CONV=4, DT_RANK=64.
// Tensor cores via mma.sync.m16n8k16 bf16x3 split (toolchain is compute_100
// base: tcgen05 unavailable).
// ---------------------------------------------------------------------------

#define BB       2
#define LL       1024
#define DMODEL   1024
#define DINNER   2048
#define DSTATE   16
#define DTRANK   64
#define MROWS    (BB * LL)                  // 2048
#define XPROJ_N  (DTRANK + 2 * DSTATE)      // 96
#define KSPLITS  8

// ------------------------- scratch (device globals) ------------------------
__device__ float g_xz[MROWS * 2 * DINNER];      // [M, 4096]
__device__ float g_u[MROWS * DINNER];           // [M, 2048]
__device__ float g_xdbl[MROWS * XPROJ_N];       // [M, 96]
__device__ float g_xpart[KSPLITS * MROWS * XPROJ_N];  // xproj split-K partials
__device__ float g_part[2 * MROWS * DMODEL];    // GEMM4 split-K partials

// bf16 split operands
__device__ __nv_bfloat16 g_xh[MROWS * DMODEL];
__device__ __nv_bfloat16 g_xl[MROWS * DMODEL];
__device__ __nv_bfloat16 g_winT_h[4096 * DMODEL];
__device__ __nv_bfloat16 g_winT_l[4096 * DMODEL];
__device__ __nv_bfloat16 g_yh[MROWS * DINNER];
__device__ __nv_bfloat16 g_yl[MROWS * DINNER];
__device__ __nv_bfloat16 g_woutT_h[DMODEL * DINNER];
__device__ __nv_bfloat16 g_woutT_l[DMODEL * DINNER];

// ---------------------------------------------------------------------------
// mma.sync / ldmatrix / cp.async helpers
// ---------------------------------------------------------------------------
__device__ __forceinline__ uint32_t smem_u32(const void* p) {
    uint32_t a;
    asm("{ .reg .u64 t; cvta.to.shared.u64 t, %1; cvt.u32.u64 %0, t; }" : "=r"(a) : "l"(p));
    return a;
}
__device__ __forceinline__ void cpa16(uint32_t s, const void* g) {
    asm volatile("cp.async.cg.shared.global [%0], [%1], 16;" :: "r"(s), "l"(g));
}
__device__ __forceinline__ void ldsm4(uint32_t& r0, uint32_t& r1, uint32_t& r2, uint32_t& r3,
                                      uint32_t addr) {
    asm volatile("ldmatrix.sync.aligned.m8n8.x4.shared.b16 {%0,%1,%2,%3}, [%4];"
                 : "=r"(r0), "=r"(r1), "=r"(r2), "=r"(r3) : "r"(addr));
}
__device__ __forceinline__ void mma16816(float& c0, float& c1, float& c2, float& c3,
                                         uint32_t a0, uint32_t a1, uint32_t a2, uint32_t a3,
                                         uint32_t b0, uint32_t b1) {
    asm volatile(
        "mma.sync.aligned.m16n8k16.row.col.f32.bf16.bf16.f32 "
        "{%0,%1,%2,%3}, {%4,%5,%6,%7}, {%8,%9}, {%0,%1,%2,%3};"
        : "+f"(c0), "+f"(c1), "+f"(c2), "+f"(c3)
        : "r"(a0), "r"(a1), "r"(a2), "r"(a3), "r"(b0), "r"(b1));
}

// ---------------------------------------------------------------------------
// bf16x3 split tensor-core GEMM:  C[M,N] = (Ah+Al)[M,K] @ (Bh+Bl)^T
//   A row-major [M][K], B as Bt[N][K] (K-major).  CTA: 256 thr = 8 warps
//   (2 M x 4 N), tile 128x128, warp tile 64x32, BK=32, cp.async double
//   buffer, 2 CTAs/SM.  Terms: AhBh + AhBl + AlBh, fp32 accumulate.
//   gridDim.z splits K deterministically; z writes C + z*partStride.
// ---------------------------------------------------------------------------
#define SSTR     40                                  // smem row stride (bf16)
#define TILE_B   (128 * SSTR * 2)                    // 10240 B per tile
#define STAGE_B  (4 * TILE_B)                        // Ah, Al, Bh, Bl
#define GM_SMEM  (2 * STAGE_B)                       // 81920 B

__device__ __forceinline__ void load_stage_tile(
    const __nv_bfloat16* __restrict__ G, int rowBase, int k0, int K,
    uint32_t sdst, int tid)
{
#pragma unroll
    for (int i = 0; i < 2; i++) {
        int idx = tid + i * 256;            // 0..511
        int r = idx >> 2;                   // row 0..127
        int q = idx & 3;                    // 16B chunk in 64B row
        const void* g = G + (size_t)(rowBase + r) * K + k0 + q * 8;
        cpa16(sdst + (uint32_t)(r * SSTR + q * 8) * 2, g);
    }
}

__global__ __launch_bounds__(256, 2)
void gemm_mma(const __nv_bfloat16* __restrict__ Ah, const __nv_bfloat16* __restrict__ Al,
              const __nv_bfloat16* __restrict__ Bh, const __nv_bfloat16* __restrict__ Bl,
              float* __restrict__ C, int Kfull, int ldc, int kdepth,
              size_t partStride)
{
    extern __shared__ __align__(16) char dsm[];
    const uint32_t sbase = smem_u32(dsm);

    const int tid  = threadIdx.x;
    const int wid  = tid >> 5;
    const int lane = tid & 31;
    const int wm   = wid >> 2;              // 0..1  (M)
    const int wn   = wid & 3;               // 0..3  (N)
    const int bx   = blockIdx.x, by = blockIdx.y;
    const int kbase = blockIdx.z * kdepth;
    C += (size_t)blockIdx.z * partStride;

    const int aRow  = lane & 15;
    const int aCsel = (lane >> 4) * 8;
    const int bRow  = (lane & 7) + ((lane >> 4) << 3);
    const int bCsel = ((lane >> 3) & 1) * 8;

    float acc[4][4][4];
#pragma unroll
    for (int i = 0; i < 4; i++)
#pragma unroll
        for (int j = 0; j < 4; j++)
#pragma unroll
            for (int v = 0; v < 4; v++) acc[i][j][v] = 0.f;

    const int NC = kdepth >> 5;

    load_stage_tile(Ah, by * 128, kbase, Kfull, sbase + 0 * TILE_B, tid);
    load_stage_tile(Al, by * 128, kbase, Kfull, sbase + 1 * TILE_B, tid);
    load_stage_tile(Bh, bx * 128, kbase, Kfull, sbase + 2 * TILE_B, tid);
    load_stage_tile(Bl, bx * 128, kbase, Kfull, sbase + 3 * TILE_B, tid);
    asm volatile("cp.async.commit_group;");

    for (int c = 0; c < NC; c++) {
        if (c + 1 < NC) {
            const uint32_t sd = sbase + ((c + 1) & 1) * STAGE_B;
            const int k0 = kbase + ((c + 1) << 5);
            load_stage_tile(Ah, by * 128, k0, Kfull, sd + 0 * TILE_B, tid);
            load_stage_tile(Al, by * 128, k0, Kfull, sd + 1 * TILE_B, tid);
            load_stage_tile(Bh, bx * 128, k0, Kfull, sd + 2 * TILE_B, tid);
            load_stage_tile(Bl, bx * 128, k0, Kfull, sd + 3 * TILE_B, tid);
            asm volatile("cp.async.commit_group;");
            asm volatile("cp.async.wait_group 1;");
        } else {
            asm volatile("cp.async.wait_group 0;");
        }
        __syncthreads();

        const uint32_t st = sbase + (c & 1) * STAGE_B;
        const uint32_t sAh = st + 0 * TILE_B;
        const uint32_t sAl = st + 1 * TILE_B;
        const uint32_t sBh = st + 2 * TILE_B;
        const uint32_t sBl = st + 3 * TILE_B;

#pragma unroll
        for (int kk = 0; kk < 32; kk += 16) {
            uint32_t ah[4][4], al[4][4], bh[2][4], bl[2][4];
#pragma unroll
            for (int i = 0; i < 4; i++) {
                uint32_t off = (uint32_t)((wm * 64 + i * 16 + aRow) * SSTR + kk + aCsel) * 2;
                ldsm4(ah[i][0], ah[i][1], ah[i][2], ah[i][3], sAh + off);
            }
#pragma unroll
            for (int j2 = 0; j2 < 2; j2++) {
                uint32_t off = (uint32_t)((wn * 32 + j2 * 16 + bRow) * SSTR + kk + bCsel) * 2;
                ldsm4(bh[j2][0], bh[j2][1], bh[j2][2], bh[j2][3], sBh + off);
            }
            // hh
#pragma unroll
            for (int i = 0; i < 4; i++)
#pragma unroll
                for (int j = 0; j < 4; j++) {
                    const uint32_t* b = bh[j >> 1] + (j & 1) * 2;
                    mma16816(acc[i][j][0], acc[i][j][1], acc[i][j][2], acc[i][j][3],
                             ah[i][0], ah[i][1], ah[i][2], ah[i][3], b[0], b[1]);
                }
            // hl
#pragma unroll
            for (int j2 = 0; j2 < 2; j2++) {
                uint32_t off = (uint32_t)((wn * 32 + j2 * 16 + bRow) * SSTR + kk + bCsel) * 2;
                ldsm4(bl[j2][0], bl[j2][1], bl[j2][2], bl[j2][3], sBl + off);
            }
#pragma unroll
            for (int i = 0; i < 4; i++)
#pragma unroll
                for (int j = 0; j < 4; j++) {
                    const uint32_t* b = bl[j >> 1] + (j & 1) * 2;
                    mma16816(acc[i][j][0], acc[i][j][1], acc[i][j][2], acc[i][j][3],
                             ah[i][0], ah[i][1], ah[i][2], ah[i][3], b[0], b[1]);
                }
            // lh
#pragma unroll
            for (int i = 0; i < 4; i++) {
                uint32_t off = (uint32_t)((wm * 64 + i * 16 + aRow) * SSTR + kk + aCsel) * 2;
                ldsm4(al[i][0], al[i][1], al[i][2], al[i][3], sAl + off);
            }
#pragma unroll
            for (int i = 0; i < 4; i++)
#pragma unroll
                for (int j = 0; j < 4; j++) {
                    const uint32_t* b = bh[j >> 1] + (j & 1) * 2;
                    mma16816(acc[i][j][0], acc[i][j][1], acc[i][j][2], acc[i][j][3],
                             al[i][0], al[i][1], al[i][2], al[i][3], b[0], b[1]);
                }
        }
        __syncthreads();
    }

    const int mBase = by * 128 + wm * 64;
    const int nBase = bx * 128 + wn * 32;
    const int r0 = lane >> 2;
    const int c0 = (lane & 3) * 2;
#pragma unroll
    for (int i = 0; i < 4; i++) {
#pragma unroll
        for (int j = 0; j < 4; j++) {
            float* p0 = C + (size_t)(mBase + i * 16 + r0) * ldc + nBase + j * 8 + c0;
            *(float2*)p0                     = make_float2(acc[i][j][0], acc[i][j][1]);
            *(float2*)(p0 + (size_t)8 * ldc) = make_float2(acc[i][j][2], acc[i][j][3]);
        }
    }
}

// fixed-order split-K reduce: out = part[0..n) + part[n..2n)  (float4)
__global__ __launch_bounds__(256)
void reduce2(const float* __restrict__ part, float* __restrict__ out, int n)
{
    int i = (blockIdx.x * 256 + threadIdx.x) * 4;
    if (i >= n) return;
    float4 a = *(const float4*)(part + i);
    float4 b = *(const float4*)(part + (size_t)n + i);
    float4 r = make_float4(a.x + b.x, a.y + b.y, a.z + b.z, a.w + b.w);
    *(float4*)(out + i) = r;
}

// ---------------------------------------------------------------------------
// fp32 -> bf16 hi/lo split (row-major)
// ---------------------------------------------------------------------------
__global__ __launch_bounds__(256)
void split_fp32_bf16(const float* __restrict__ in, __nv_bfloat16* __restrict__ hi,
                     __nv_bfloat16* __restrict__ lo, int n)
{
    int i = blockIdx.x * 256 + threadIdx.x;
    if (i >= n) return;
    float a = in[i];
    __nv_bfloat16 h = __float2bfloat16(a);
    hi[i] = h;
    lo[i] = __float2bfloat16(a - __bfloat162float(h));
}

// transpose + split:  in[K][N] fp32  ->  hiT/loT [N][K] bf16
__global__ __launch_bounds__(256)
void tsplit_fp32_bf16(const float* __restrict__ in,
                      __nv_bfloat16* __restrict__ hiT, __nv_bfloat16* __restrict__ loT,
                      int K, int N)
{
    __shared__ float t[32][33];
    int tx = threadIdx.x & 31;
    int ty = threadIdx.x >> 5;
    int n0 = blockIdx.x * 32;
    int k0 = blockIdx.y * 32;
#pragma unroll
    for (int j = 0; j < 4; j++) {
        int kk = ty + j * 8;
        t[kk][tx] = in[(size_t)(k0 + kk) * N + n0 + tx];
    }
    __syncthreads();
#pragma unroll
    for (int j = 0; j < 4; j++) {
        int a = ty + j * 8;
        float v = t[tx][a];
        __nv_bfloat16 h = __float2bfloat16(v);
        hiT[(size_t)(n0 + a) * K + k0 + tx] = h;
        loT[(size_t)(n0 + a) * K + k0 + tx] = __float2bfloat16(v - __bfloat162float(h));
    }
}

// ---------------------------------------------------------------------------
// depthwise conv(4) + bias + silu, float4-vectorized over channels
// ---------------------------------------------------------------------------
__global__ __launch_bounds__(256)
void conv_silu_kernel(const float* __restrict__ xz,
                      const float* __restrict__ cw,
                      const float* __restrict__ cb,
                      float* __restrict__ u)
{
    int idx = blockIdx.x * blockDim.x + threadIdx.x;   // over M*DINNER/4
    if (idx >= MROWS * DINNER / 4) return;
    int d4  = (idx & (DINNER / 4 - 1)) * 4;
    int row = idx >> 9;
    int l   = row & (LL - 1);

    float4 w0 = *(const float4*)(cw + d4 * 4 + 0);
    float4 w1 = *(const float4*)(cw + d4 * 4 + 4);
    float4 w2 = *(const float4*)(cw + d4 * 4 + 8);
    float4 w3 = *(const float4*)(cw + d4 * 4 + 12);
    float4 bias = *(const float4*)(cb + d4);

    const float* base = xz + (size_t)row * (2 * DINNER) + d4;
    const int stride = 2 * DINNER;

    float4 s = bias;
    if (l >= 3) {
        float4 v = *(const float4*)(base - 3 * stride);
        s.x += v.x * w0.x; s.y += v.y * w1.x; s.z += v.z * w2.x; s.w += v.w * w3.x;
    }
    if (l >= 2) {
        float4 v = *(const float4*)(base - 2 * stride);
        s.x += v.x * w0.y; s.y += v.y * w1.y; s.z += v.z * w2.y; s.w += v.w * w3.y;
    }
    if (l >= 1) {
        float4 v = *(const float4*)(base - 1 * stride);
        s.x += v.x * w0.z; s.y += v.y * w1.z; s.z += v.z * w2.z; s.w += v.w * w3.z;
    }
    {
        float4 v = *(const float4*)(base);
        s.x += v.x * w0.w; s.y += v.y * w1.w; s.z += v.z * w2.w; s.w += v.w * w3.w;
    }
    float4 r;
    r.x = s.x / (1.f + expf(-s.x));
    r.y = s.y / (1.f + expf(-s.y));
    r.z = s.z / (1.f + expf(-s.z));
    r.w = s.w / (1.f + expf(-s.w));
    *(float4*)(u + (size_t)row * DINNER + d4) = r;
}

// ---------------------------------------------------------------------------
// xproj split-K:  part[ks] = u[:, ks*256:(ks+1)*256] @ W_xproj[ks*256.., :]
// ---------------------------------------------------------------------------
__global__ __launch_bounds__(256)
void xprojA(const float* __restrict__ u, const float* __restrict__ W,
            float* __restrict__ part)
{
    __shared__ float As[64 * 32];      // [r][k], stride 32
    __shared__ float Bs[96 * 36];      // [c][k], stride 36

    const int ks = blockIdx.x;
    const int mb = blockIdx.y;
    const int tid = threadIdx.x;
    const int rg = tid >> 4;
    const int cg = tid & 15;

    float acc[4][6];
#pragma unroll
    for (int r = 0; r < 4; r++)
#pragma unroll
        for (int j = 0; j < 6; j++) acc[r][j] = 0.f;

    for (int kc = 0; kc < 8; kc++) {
        const int kbase = ks * 256 + kc * 32;
#pragma unroll
        for (int i = tid; i < 64 * 32; i += 256) {
            int r = i >> 5, k = i & 31;
            As[r * 32 + k] = u[(size_t)(mb * 64 + r) * DINNER + kbase + k];
        }
#pragma unroll
        for (int i = tid; i < 96 * 32; i += 256) {
            int c = i % 96, k = i / 96;
            Bs[c * 36 + k] = W[(size_t)(kbase + k) * XPROJ_N + c];
        }
        __syncthreads();
#pragma unroll
        for (int kq = 0; kq < 8; kq++) {
            float4 a[4], b[6];
#pragma unroll
            for (int r = 0; r < 4; r++)
                a[r] = *(const float4*)&As[(rg * 4 + r) * 32 + kq * 4];
#pragma unroll
            for (int j = 0; j < 6; j++)
                b[j] = *(const float4*)&Bs[(j * 16 + cg) * 36 + kq * 4];
#pragma unroll
            for (int r = 0; r < 4; r++)
#pragma unroll
                for (int j = 0; j < 6; j++)
                    acc[r][j] += a[r].x * b[j].x + a[r].y * b[j].y
                               + a[r].z * b[j].z + a[r].w * b[j].w;
        }
        __syncthreads();
    }
#pragma unroll
    for (int r = 0; r < 4; r++)
#pragma unroll
        for (int j = 0; j < 6; j++)
            part[((size_t)ks * MROWS + mb * 64 + rg * 4 + r) * XPROJ_N + j * 16 + cg]
                = acc[r][j];
}

__global__ __launch_bounds__(256)
void xprojB(const float* __restrict__ part, float* __restrict__ xdbl)
{
    int idx = blockIdx.x * 256 + threadIdx.x;
    if (idx >= MROWS * XPROJ_N) return;
    float s = 0.f;
#pragma unroll
    for (int ks = 0; ks < KSPLITS; ks++)
        s += part[(size_t)ks * MROWS * XPROJ_N + idx];
    xdbl[idx] = s;
}

// ---------------------------------------------------------------------------
// selective scan, latency-optimized:
//   - fused delta GEMM (dt_lr @ W_dt + b_dt -> softplus)
//   - serial phase has ONLY h = dA*h + dBu on the critical path; per-step
//     products p = h*c go to padded smem (STS, off-path)
//   - separate parallel reduction over n emits y -> bf16 hi/lo
// Chunk = 32 timesteps.  Dynamic smem.
// ---------------------------------------------------------------------------
#define SCT 32
// float offsets into dynamic smem
#define OFF_W     0                       // [64][16]     1024
#define OFF_BD    1024                    // [16]
#define OFF_DSK   1040                    // [16]
#define OFF_DT    1056                    // [32][64]     2048
#define OFF_DEL   3104                    // [32][16]     512
#define OFF_U     3616                    // [32][16]     512
#define OFF_Z     4128                    // [32][16]     512
#define OFF_B     4640                    // [32][16]     512
#define OFF_C     5152                    // [32][16]     512
#define OFF_P     5664                    // [32][16][17] 8704
#define SCAN_SMEM ((5664 + 8704) * 4)     // 57472 bytes

__global__ __launch_bounds__(256)
void scan_kernel(const float* __restrict__ u,
                 const float* __restrict__ xz,
                 const float* __restrict__ xdbl,
                 const float* __restrict__ W_dt,   // [64, 2048]
                 const float* __restrict__ b_dt,   // [2048]
                 const float* __restrict__ A_log,
                 const float* __restrict__ Dskip,
                 __nv_bfloat16* __restrict__ yh,
                 __nv_bfloat16* __restrict__ yl)
{
    extern __shared__ float sm[];
    float* sW   = sm + OFF_W;
    float* sbd  = sm + OFF_BD;
    float* sdsk = sm + OFF_DSK;
    float* sDT  = sm + OFF_DT;
    float* sDel = sm + OFF_DEL;
    float* sU   = sm + OFF_U;
    float* sZ   = sm + OFF_Z;
    float* sB   = sm + OFF_B;
    float* sC   = sm + OFF_C;
    float* sP   = sm + OFF_P;

    const int tid = threadIdx.x;
    const int tn = tid & 15;
    const int td = tid >> 4;
    const int dbase = blockIdx.x * 16;
    const int b = blockIdx.y;

    for (int i = tid; i < 64 * 16; i += 256) {
        int r = i >> 4, c = i & 15;
        sW[i] = W_dt[(size_t)r * DINNER + dbase + c];
    }
    if (tid < 16) {
        sbd[tid]  = b_dt[dbase + tid];
        sdsk[tid] = Dskip[dbase + tid];
    }
    const float Aq = -expf(A_log[(dbase + td) * DSTATE + tn]);
    __syncthreads();

    float h = 0.f;

    for (int t0 = 0; t0 < LL; t0 += SCT) {
        // ---- stage ----
#pragma unroll
        for (int i = tid; i < SCT * 16; i += 256) {     // 2 iters
            int r = i >> 4, c = i & 15;
            int row = b * LL + t0 + r;
            sU[i] = u[(size_t)row * DINNER + dbase + c];
            sZ[i] = xz[(size_t)row * (2 * DINNER) + DINNER + dbase + c];
            sB[i] = xdbl[(size_t)row * XPROJ_N + DTRANK + c];
            sC[i] = xdbl[(size_t)row * XPROJ_N + DTRANK + DSTATE + c];
        }
#pragma unroll
        for (int i = tid; i < SCT * 64; i += 256) {     // 8 iters
            int r = i >> 6, k = i & 63;
            sDT[i] = xdbl[(size_t)(b * LL + t0 + r) * XPROJ_N + k];
        }
        __syncthreads();

        // ---- fused delta (2 outputs/thread; same col, rows r and r+16) ----
        {
            const int c = tid & 15;
            const int r0 = tid >> 4;
            float s0 = sbd[c], s1 = sbd[c];
#pragma unroll 8
            for (int k = 0; k < 64; k++) {
                float w = sW[k * 16 + c];
                s0 += sDT[r0 * 64 + k] * w;
                s1 += sDT[(r0 + 16) * 64 + k] * w;
            }
            sDel[r0 * 16 + c]        = (s0 > 20.f) ? s0 : log1pf(expf(s0));
            sDel[(r0 + 16) * 16 + c] = (s1 > 20.f) ? s1 : log1pf(expf(s1));
        }
        __syncthreads();

        // ---- serial recurrence: critical path = 1 FFMA/step ----
#pragma unroll 8
        for (int tt = 0; tt < SCT; tt++) {
            float dlt = sDel[tt * 16 + td];
            float uu  = sU[tt * 16 + td];
            float bb  = sB[tt * 16 + tn];
            float cc  = sC[tt * 16 + tn];
            float dA  = __expf(dlt * Aq);
            h = dA * h + (dlt * uu) * bb;
            sP[(tt * 16 + td) * 17 + tn] = h * cc;
        }
        __syncthreads();

        // ---- parallel reduce over n + gate + bf16 split output ----
#pragma unroll
        for (int v = 0; v < 2; v++) {
            int o = tid + v * 256;
            int tt = o >> 4, c = o & 15;
            const float* p = sP + (tt * 16 + c) * 17;
            float s = 0.f;
#pragma unroll
            for (int n = 0; n < 16; n++) s += p[n];
            float uu = sU[tt * 16 + c];
            float zz = sZ[tt * 16 + c];
            float yv = s + sdsk[c] * uu;
            yv *= zz / (1.f + expf(-zz));
            int row = b * LL + t0 + tt;
            __nv_bfloat16 hb = __float2bfloat16(yv);
            yh[(size_t)row * DINNER + dbase + c] = hb;
            yl[(size_t)row * DINNER + dbase + c] =
                __float2bfloat16(yv - __bfloat162float(hb));
        }
        __syncthreads();
    }
}

// ---------------------------------------------------------------------------
extern "C" void kernel_launch(void* const* d_in, const int* in_sizes, int n_in,
                              void* d_out, int out_size)
{
    const float* x       = (const float*)d_in[0];  // [2,1024,1024]
    const float* W_in    = (const float*)d_in[1];  // [1024, 4096]
    const float* conv_w  = (const float*)d_in[2];  // [2048, 1, 4]
    const float* conv_b  = (const float*)d_in[3];  // [2048]
    const float* W_xproj = (const float*)d_in[4];  // [2048, 96]
    const float* W_dt    = (const float*)d_in[5];  // [64, 2048]
    const float* b_dt    = (const float*)d_in[6];  // [2048]
    const float* A_log   = (const float*)d_in[7];  // [2048, 16]
    const float* D_skip  = (const float*)d_in[8];  // [2048]
    const float* W_out   = (const float*)d_in[9];  // [2048, 1024]
    float* out = (float*)d_out;                    // [2,1024,1024]

    float* xz;    cudaGetSymbolAddress((void**)&xz,    g_xz);
    float* u;     cudaGetSymbolAddress((void**)&u,     g_u);
    float* xdbl;  cudaGetSymbolAddress((void**)&xdbl,  g_xdbl);
    float* xpart; cudaGetSymbolAddress((void**)&xpart, g_xpart);
    float* part;  cudaGetSymbolAddress((void**)&part,  g_part);

    __nv_bfloat16 *xh, *xl, *winTh, *winTl, *yh, *yl, *woutTh, *woutTl;
    cudaGetSymbolAddress((void**)&xh,     g_xh);
    cudaGetSymbolAddress((void**)&xl,     g_xl);
    cudaGetSymbolAddress((void**)&winTh,  g_winT_h);
    cudaGetSymbolAddress((void**)&winTl,  g_winT_l);
    cudaGetSymbolAddress((void**)&yh,     g_yh);
    cudaGetSymbolAddress((void**)&yl,     g_yl);
    cudaGetSymbolAddress((void**)&woutTh, g_woutT_h);
    cudaGetSymbolAddress((void**)&woutTl, g_woutT_l);

    cudaFuncSetAttribute(gemm_mma, cudaFuncAttributeMaxDynamicSharedMemorySize, GM_SMEM);
    cudaFuncSetAttribute(scan_kernel, cudaFuncAttributeMaxDynamicSharedMemorySize, SCAN_SMEM);

    // operand conversions
    split_fp32_bf16<<<(MROWS * DMODEL) / 256, 256>>>(x, xh, xl, MROWS * DMODEL);
    tsplit_fp32_bf16<<<dim3(4096 / 32, DMODEL / 32), 256>>>(W_in, winTh, winTl, DMODEL, 4096);
    tsplit_fp32_bf16<<<dim3(DMODEL / 32, DINNER / 32), 256>>>(W_out, woutTh, woutTl, DINNER, DMODEL);

    // 1) xz = x @ W_in        [2048,1024] @ [1024,4096]   (tensor cores)
    gemm_mma<<<dim3(4096 / 128, MROWS / 128, 1), 256, GM_SMEM>>>(
        xh, xl, winTh, winTl, xz, DMODEL, 4096, DMODEL, 0);

    // 2) u = silu(conv(xz[:, :2048]) + conv_b)
    conv_silu_kernel<<<(MROWS * DINNER / 4 + 255) / 256, 256>>>(xz, conv_w, conv_b, u);

    // 3) xdbl = u @ W_xproj   (deterministic split-K)
    xprojA<<<dim3(KSPLITS, MROWS / 64), 256>>>(u, W_xproj, xpart);
    xprojB<<<(MROWS * XPROJ_N + 255) / 256, 256>>>(xpart, xdbl);

    // 4+5) fused delta + selective scan -> yh/yl (bf16 split)
    scan_kernel<<<dim3(DINNER / 16, BB), 256, SCAN_SMEM>>>(
        u, xz, xdbl, W_dt, b_dt, A_log, D_skip, yh, yl);

    // 6) out = y @ W_out   [2048,2048]@[2048,1024], 2-way split-K + reduce
    gemm_mma<<<dim3(1024 / 128, MROWS / 128, 2), 256, GM_SMEM>>>(
        yh, yl, woutTh, woutTl, part, DINNER, 1024, 1024,
        (size_t)MROWS * DMODEL);
    reduce2<<<(MROWS * DMODEL / 4 + 255) / 256, 256>>>(part, out, MROWS * DMODEL);
}